// round 13
// baseline (speedup 1.0000x reference)
#include <cuda_runtime.h>

// ---------------- problem constants (raster grid 1024x1024) ----------------
#define R_  1024
#define C_  1024
#define N_  (R_ * C_)
#define HL_ (R_ * (C_ - 1))          // horizontal links = 1,047,552
#define L_  (HL_ + (R_ - 1) * C_)    // total links = 2,095,104
#define ITERS_ 15
#define NSLOT 32
#define F4ROW (C_ / 4)               // 256 float4 per row
#define TOT4  (N_ / 4)               // 262144 float4 total

#define K_FLOW_  0.0405f
#define FLOW_EXP_ 1.25f
#define A_OPEN_  1.3455e-09f
#define C_CLOSE_ 7.11e-24f
#define RWG_     9810.0f             // rho_w * g
#define INV_DX_  (1.0f / 100.0f)
#define INV_DX2_ (1.0f / (100.0f * 100.0f))

// tile: 16 rows x 32 f4 (128 floats) per block; 512 blocks; halo 1 cell
#define SROWS 18
#define SCOLS 136
#define TSLOTS (18 * 34)             // 612 haloed f4 slots

// ---------------- device scratch (static; no allocations) ----------------
__device__ __align__(16) float g_x [N_];
__device__ __align__(16) float g_r [N_];
__device__ __align__(16) float g_pA[N_];
__device__ __align__(16) float g_pB[N_];
__device__ __align__(16) float g_vA[N_];
__device__ __align__(16) float g_vB[N_];
__device__ __align__(16) float g_s [N_];
__device__ __align__(16) float g_t [N_];
__device__ __align__(16) float g_r0[N_];
__device__ __align__(16) float g_eff[N_];
__device__ __align__(16) float g_grad[L_];

// scalar slots (32 contention-spread each)
__device__ double g_rho1[NSLOT];                    // rho[1] = dot(r0,r0)
__device__ double g_dr0v[(ITERS_ + 1) * NSLOT];     // [0]=1 ; [i+1]=dot(r0,v)
__device__ double g_dts [(ITERS_ + 1) * NSLOT];     // [0]=1 ; [i+1]=dot(t,s)
__device__ double g_dtt [(ITERS_ + 1) * NSLOT];     // [0]=1 ; [i+1]=dot(t,t)
__device__ double g_dr0s[(ITERS_ + 1) * NSLOT];     // [i+1]=dot(r0,s)
__device__ double g_dr0t[(ITERS_ + 1) * NSLOT];     // [i+1]=dot(r0,t)

#define EPSD 1e-30

__device__ __forceinline__ double slotsum(const double* p) {
    double a = 0.0;
    #pragma unroll
    for (int i = 0; i < NSLOT; i++) a += p[i];
    return a;
}

// rho[k] (the reference's dot(r0, r) at start of iteration k-1)
__device__ double rho_of(int k) {
    if (k <= 0) return 1.0;
    if (k == 1) return slotsum(g_rho1);
    double om = slotsum(&g_dts[(k - 1) * NSLOT]) /
                (slotsum(&g_dtt[(k - 1) * NSLOT]) + EPSD);
    return slotsum(&g_dr0s[(k - 1) * NSLOT]) - om * slotsum(&g_dr0t[(k - 1) * NSLOT]);
}

// ---------------- reductions: f32 to warp level, f64 above ----------------
__device__ __forceinline__ void red1f(float v, double* dst) {
    #pragma unroll
    for (int o = 16; o > 0; o >>= 1) v += __shfl_down_sync(0xffffffffu, v, o);
    __shared__ double sm1[8];
    int lane = threadIdx.x & 31, w = threadIdx.x >> 5;
    if (lane == 0) sm1[w] = (double)v;
    __syncthreads();
    if (threadIdx.x < 8) {
        double d = sm1[threadIdx.x];
        #pragma unroll
        for (int o = 4; o > 0; o >>= 1) d += __shfl_down_sync(0xffu, d, o);
        if (threadIdx.x == 0) atomicAdd(dst, d);
    }
}

__device__ __forceinline__ void red4f(float a, float b, float c, float d,
                                      double* da, double* db, double* dc, double* dd) {
    #pragma unroll
    for (int o = 16; o > 0; o >>= 1) {
        a += __shfl_down_sync(0xffffffffu, a, o);
        b += __shfl_down_sync(0xffffffffu, b, o);
        c += __shfl_down_sync(0xffffffffu, c, o);
        d += __shfl_down_sync(0xffffffffu, d, o);
    }
    __shared__ double sma[8], smb[8], smc[8], smd[8];
    int lane = threadIdx.x & 31, w = threadIdx.x >> 5;
    if (lane == 0) { sma[w] = (double)a; smb[w] = (double)b;
                     smc[w] = (double)c; smd[w] = (double)d; }
    __syncthreads();
    if (threadIdx.x < 8) {
        double a_ = sma[threadIdx.x], b_ = smb[threadIdx.x];
        double c_ = smc[threadIdx.x], d_ = smd[threadIdx.x];
        #pragma unroll
        for (int o = 4; o > 0; o >>= 1) {
            a_ += __shfl_down_sync(0xffu, a_, o);
            b_ += __shfl_down_sync(0xffu, b_, o);
            c_ += __shfl_down_sync(0xffu, c_, o);
            d_ += __shfl_down_sync(0xffu, d_, o);
        }
        if (threadIdx.x == 0) {
            atomicAdd(da, a_); atomicAdd(db, b_);
            atomicAdd(dc, c_); atomicAdd(dd, d_);
        }
    }
}

__device__ __forceinline__ float dot4f(float4 a, float4 b) {
    return a.x * b.x + a.y * b.y + a.z * b.z + a.w * b.w;
}

__device__ __forceinline__ bool is_border(int r, int c) {
    return (r == 0 || r == R_ - 1 || c == 0 || c == C_ - 1);
}

// ---------------- prologue kernel: grad (float4) + scalar-slot init --------
// s^1.25 = s * sqrt(sqrt(s))
__device__ __forceinline__ float pow125(float s) {
    return s * sqrtf(sqrtf(s));
}

__global__ void __launch_bounds__(256) k_grad(const float4* __restrict__ cs,
                                              const float4* __restrict__ q,
                                              const int4* __restrict__ fd) {
    int i = blockIdx.x * blockDim.x + threadIdx.x;   // over L_/4
    if (blockIdx.x == 0) {
        for (int j = threadIdx.x; j < NSLOT; j += 256) g_rho1[j] = 0.0;
        for (int j = threadIdx.x; j < (ITERS_ + 1) * NSLOT; j += 256) {
            double v = (j == 0) ? 1.0 : 0.0;
            g_dr0v[j] = v; g_dts[j] = v; g_dtt[j] = v;
            g_dr0s[j] = 0.0; g_dr0t[j] = 0.0;
        }
    }
    if (i < L_ / 4) {
        float4 s = cs[i];
        float4 qq = q[i];
        int4  f = fd[i];
        float4 o;
        float gx = qq.x / (K_FLOW_ * pow125(s.x)); o.x = gx * gx * (float)f.x;
        float gy = qq.y / (K_FLOW_ * pow125(s.y)); o.y = gy * gy * (float)f.y;
        float gz = qq.z / (K_FLOW_ * pow125(s.z)); o.z = gz * gz * (float)f.z;
        float gw = qq.w / (K_FLOW_ * pow125(s.w)); o.w = gw * gw * (float)f.w;
        ((float4*)g_grad)[i] = o;
    }
}

// ---------------- init: r0 = b - A(0); zero x, pA, vA (vectorized) --------
__device__ __forceinline__ float xb0v(const int* __restrict__ io,
                                      const float* __restrict__ bed, int r, int c) {
    if (is_border(r, c)) {
        int n = r * C_ + c;
        if (__ldg(&io[n]) == -1) return RWG_ * __ldg(&bed[n]);
    }
    return 0.f;
}

__global__ void __launch_bounds__(256) k_init(const int* __restrict__ io,
                                              const float* __restrict__ bed) {
    int i4 = blockIdx.x * blockDim.x + threadIdx.x;   // over TOT4
    int n = i4 << 2;
    int r = n >> 10, c0 = n & (C_ - 1);

    // vertical link grads (aligned float4): down at HL_+n, up at HL_+n-C_
    float4 gv  = make_float4(0.f, 0.f, 0.f, 0.f);
    float4 gvu = make_float4(0.f, 0.f, 0.f, 0.f);
    if (r < R_ - 1) gv  = ((const float4*)g_grad)[(HL_ + n) >> 2];
    if (r > 0)      gvu = ((const float4*)g_grad)[(HL_ + n - C_) >> 2];
    // horizontal link grads: row base r*(C_-1), scalars c0-1 .. c0+3
    int hb = r * (C_ - 1);
    float ghm = (c0 > 0) ? __ldg(&g_grad[hb + c0 - 1]) : 0.f;
    float gh0 = __ldg(&g_grad[hb + c0 + 0]);
    float gh1 = __ldg(&g_grad[hb + c0 + 1]);
    float gh2 = __ldg(&g_grad[hb + c0 + 2]);
    float gh3 = (c0 + 3 < C_ - 1) ? __ldg(&g_grad[hb + c0 + 3]) : 0.f;

    float4 r0v;
    #pragma unroll
    for (int j = 0; j < 4; j++) {
        int c = c0 + j;
        float ghR = (j == 0) ? gh0 : (j == 1) ? gh1 : (j == 2) ? gh2 : gh3;
        float ghL = (j == 0) ? ghm : (j == 1) ? gh0 : (j == 2) ? gh1 : gh2;
        float gvD = ((const float*)&gv)[j];
        float gvU = ((const float*)&gvu)[j];
        // same add order as before: +right, +down, -left, -up
        float acc = 0.f;
        if (c < C_ - 1) acc += ghR;
        if (r < R_ - 1) acc += gvD;
        if (c > 0)      acc -= ghL;
        if (r > 0)      acc -= gvU;
        float b = acc * INV_DX_;
        // A(0): only nonzero near borders (same expression as before)
        float xc = xb0v(io, bed, r, c);
        float a = 0.f;
        if (c > 0)      a += xb0v(io, bed, r, c - 1) - xc;
        if (c < C_ - 1) a += xb0v(io, bed, r, c + 1) - xc;
        if (r > 0)      a += xb0v(io, bed, r - 1, c) - xc;
        if (r < R_ - 1) a += xb0v(io, bed, r + 1, c) - xc;
        ((float*)&r0v)[j] = b - a * INV_DX2_;
    }
    ((float4*)g_r0)[i4] = r0v;
    ((float4*)g_r )[i4] = r0v;
    float4 z = make_float4(0.f, 0.f, 0.f, 0.f);
    ((float4*)g_x )[i4] = z;
    ((float4*)g_pA)[i4] = z;
    ((float4*)g_vA)[i4] = z;
    red1f(dot4f(r0v, r0v), &g_rho1[blockIdx.x & (NSLOT - 1)]);
}

// ---------------- K_A: r_cur = s - om_p*t (it>=1) ; x += al_p*p + om_p*s ;
//    p_new = r_cur + beta*(p_old - om_p*v_old) ; v_new = A(xb(p_new)) ;
//    dot(r0, v_new) --------------------------------------------------------
__global__ void __launch_bounds__(256, 4) k_A(const int* __restrict__ io,
                                              const float* __restrict__ bed,
                                              int it) {
    int pp = it & 1;
    const float* __restrict__ pOld = pp ? g_pB : g_pA;
    const float* __restrict__ vOld = pp ? g_vB : g_vA;
    float* __restrict__ pNew = pp ? g_pA : g_pB;
    float* __restrict__ vNew = pp ? g_vA : g_vB;
    const bool first = (it == 0);

    __shared__ float sP [SROWS][SCOLS];   // substituted p_new (stencil input)
    __shared__ float sRN[SROWS][SCOLS];   // raw r_new
    __shared__ float sSV[SROWS][SCOLS];   // raw s (prev iter)
    __shared__ float shs[3];
    if (threadIdx.x == 0) {
        double om_p  = slotsum(&g_dts[it * NSLOT]) /
                       (slotsum(&g_dtt[it * NSLOT]) + EPSD);
        double rho_p = rho_of(it);
        double al_p  = rho_p / (slotsum(&g_dr0v[it * NSLOT]) + EPSD);
        double rho_n = rho_of(it + 1);
        shs[0] = (float)((rho_n / (rho_p + EPSD)) * (al_p / (om_p + EPSD)));  // beta
        shs[1] = (float)om_p;
        shs[2] = (float)al_p;
    }
    __syncthreads();
    float beta = shs[0], om = shs[1], al = shs[2];

    int b = blockIdx.x;                  // 512 blocks: 64 tile-rows x 8 tile-cols
    int tx = b & 7, ty = b >> 3;
    int row0 = ty << 4, col4 = tx << 5;
    bool edge = (ty == 0) || (ty == 63) || (tx == 0) || (tx == 7);

    // fill smem with xb-substituted p_new over haloed region; stash raw rn, sv
    for (int slot = threadIdx.x; slot < TSLOTS; slot += 256) {
        int hr = slot / 34, hc = slot - hr * 34;
        int grow = row0 - 1 + hr;
        int g4c  = col4 - 1 + hc;
        if ((unsigned)grow > (unsigned)(R_ - 1) ||
            (unsigned)g4c  > (unsigned)(F4ROW - 1)) continue;
        int i4 = (grow << 8) + g4c;
        float4 pv = ((const float4*)pOld)[i4];
        float4 vv = ((const float4*)vOld)[i4];
        float4 rn;
        int sc = hc << 2;
        if (first) {
            rn = ((const float4*)g_r)[i4];
        } else {
            float4 sv = ((const float4*)g_s)[i4];
            float4 tv = ((const float4*)g_t)[i4];
            rn.x = sv.x - om * tv.x;  rn.y = sv.y - om * tv.y;
            rn.z = sv.z - om * tv.z;  rn.w = sv.w - om * tv.w;
            sSV[hr][sc + 0] = sv.x;  sSV[hr][sc + 1] = sv.y;
            sSV[hr][sc + 2] = sv.z;  sSV[hr][sc + 3] = sv.w;
        }
        sRN[hr][sc + 0] = rn.x;  sRN[hr][sc + 1] = rn.y;
        sRN[hr][sc + 2] = rn.z;  sRN[hr][sc + 3] = rn.w;
        float vals[4];
        vals[0] = rn.x + beta * (pv.x - om * vv.x);
        vals[1] = rn.y + beta * (pv.y - om * vv.y);
        vals[2] = rn.z + beta * (pv.z - om * vv.z);
        vals[3] = rn.w + beta * (pv.w - om * vv.w);
        if (edge) {
            int nb = (grow << 10) + (g4c << 2);
            #pragma unroll
            for (int j = 0; j < 4; j++) {
                int gc = (g4c << 2) + j;
                if (is_border(grow, gc) && __ldg(&io[nb + j]) == -1)
                    vals[j] = RWG_ * __ldg(&bed[nb + j]);
            }
        }
        sP[hr][sc + 0] = vals[0];
        sP[hr][sc + 1] = vals[1];
        sP[hr][sc + 2] = vals[2];
        sP[hr][sc + 3] = vals[3];
    }
    __syncthreads();

    // two output rows per thread: r_i and r_i + 8
    int r_i = threadIdx.x >> 5, c_i = threadIdx.x & 31;
    int g4c = col4 + c_i;
    int gc0 = g4c << 2;
    float acc = 0.f;
    #pragma unroll
    for (int k = 0; k < 2; k++) {
        int grow = row0 + r_i + (k << 3);
        int i4 = (grow << 8) + g4c;
        int hr = r_i + 1 + (k << 3), sc = (c_i + 1) << 2;
        float4 pv = ((const float4*)pOld)[i4];
        float4 vv = ((const float4*)vOld)[i4];
        float4 rn;
        if (first) {
            rn = ((const float4*)g_r)[i4];
        } else if (!edge) {
            // raw rn / sv from smem stash (same expressions, same inputs)
            rn.x = sRN[hr][sc + 0];  rn.y = sRN[hr][sc + 1];
            rn.z = sRN[hr][sc + 2];  rn.w = sRN[hr][sc + 3];
            ((float4*)g_r)[i4] = rn;
            float4 xv = ((const float4*)g_x)[i4];
            float4 xn;
            xn.x = (xv.x + al * pv.x) + om * sSV[hr][sc + 0];
            xn.y = (xv.y + al * pv.y) + om * sSV[hr][sc + 1];
            xn.z = (xv.z + al * pv.z) + om * sSV[hr][sc + 2];
            xn.w = (xv.w + al * pv.w) + om * sSV[hr][sc + 3];
            ((float4*)g_x)[i4] = xn;
        } else {
            float4 sv = ((const float4*)g_s)[i4];
            float4 tv = ((const float4*)g_t)[i4];
            rn.x = sv.x - om * tv.x;  rn.y = sv.y - om * tv.y;
            rn.z = sv.z - om * tv.z;  rn.w = sv.w - om * tv.w;
            ((float4*)g_r)[i4] = rn;
            float4 xv = ((const float4*)g_x)[i4];
            float4 xn;
            xn.x = (xv.x + al * pv.x) + om * sv.x;
            xn.y = (xv.y + al * pv.y) + om * sv.y;
            xn.z = (xv.z + al * pv.z) + om * sv.z;
            xn.w = (xv.w + al * pv.w) + om * sv.w;
            ((float4*)g_x)[i4] = xn;
        }
        float4 pn;
        pn.x = rn.x + beta * (pv.x - om * vv.x);
        pn.y = rn.y + beta * (pv.y - om * vv.y);
        pn.z = rn.z + beta * (pv.z - om * vv.z);
        pn.w = rn.w + beta * (pv.w - om * vv.w);
        ((float4*)pNew)[i4] = pn;

        float4 vout;
        if (!edge) {
            #pragma unroll
            for (int j = 0; j < 4; j++) {
                float xc = sP[hr][sc + j];
                float a = (sP[hr][sc + j - 1] - xc);
                a += (sP[hr][sc + j + 1] - xc);
                a += (sP[hr - 1][sc + j] - xc);
                a += (sP[hr + 1][sc + j] - xc);
                ((float*)&vout)[j] = a * INV_DX2_;
            }
        } else {
            #pragma unroll
            for (int j = 0; j < 4; j++) {
                float xc = sP[hr][sc + j];
                float a = 0.f;
                int gc = gc0 + j;
                if (gc > 0)          a += sP[hr][sc + j - 1] - xc;
                if (gc < C_ - 1)     a += sP[hr][sc + j + 1] - xc;
                if (grow > 0)        a += sP[hr - 1][sc + j] - xc;
                if (grow < R_ - 1)   a += sP[hr + 1][sc + j] - xc;
                ((float*)&vout)[j] = a * INV_DX2_;
            }
        }
        ((float4*)vNew)[i4] = vout;
        acc += dot4f(((const float4*)g_r0)[i4], vout);
    }
    red1f(acc, &g_dr0v[(it + 1) * NSLOT + (blockIdx.x & (NSLOT - 1))]);
}

// ---------------- K_B: s = r - al*v ; t = A(xb(s)) ;
//    dots (t,s),(t,t),(r0,s),(r0,t) -----------------------------------------
__global__ void __launch_bounds__(256, 4) k_B(const int* __restrict__ io,
                                              const float* __restrict__ bed,
                                              int it) {
    int pp = it & 1;
    const float* __restrict__ v = pp ? g_vA : g_vB;   // v_new of this iter

    __shared__ float sS [SROWS][SCOLS];   // substituted s (stencil input)
    __shared__ float sSR[SROWS][SCOLS];   // raw s
    __shared__ float shs[1];
    if (threadIdx.x == 0) {
        double rho_n = rho_of(it + 1);
        shs[0] = (float)(rho_n / (slotsum(&g_dr0v[(it + 1) * NSLOT]) + EPSD));
    }
    __syncthreads();
    float al = shs[0];

    int b = blockIdx.x;
    int tx = b & 7, ty = b >> 3;
    int row0 = ty << 4, col4 = tx << 5;
    bool edge = (ty == 0) || (ty == 63) || (tx == 0) || (tx == 7);

    for (int slot = threadIdx.x; slot < TSLOTS; slot += 256) {
        int hr = slot / 34, hc = slot - hr * 34;
        int grow = row0 - 1 + hr;
        int g4c  = col4 - 1 + hc;
        if ((unsigned)grow > (unsigned)(R_ - 1) ||
            (unsigned)g4c  > (unsigned)(F4ROW - 1)) continue;
        int i4 = (grow << 8) + g4c;
        float4 rv = ((const float4*)g_r)[i4];
        float4 vv = ((const float4*)v)[i4];
        float vals[4];
        vals[0] = rv.x - al * vv.x;
        vals[1] = rv.y - al * vv.y;
        vals[2] = rv.z - al * vv.z;
        vals[3] = rv.w - al * vv.w;
        int sc = hc << 2;
        sSR[hr][sc + 0] = vals[0];
        sSR[hr][sc + 1] = vals[1];
        sSR[hr][sc + 2] = vals[2];
        sSR[hr][sc + 3] = vals[3];
        if (edge) {
            int nb = (grow << 10) + (g4c << 2);
            #pragma unroll
            for (int j = 0; j < 4; j++) {
                int gc = (g4c << 2) + j;
                if (is_border(grow, gc) && __ldg(&io[nb + j]) == -1)
                    vals[j] = RWG_ * __ldg(&bed[nb + j]);
            }
        }
        sS[hr][sc + 0] = vals[0];
        sS[hr][sc + 1] = vals[1];
        sS[hr][sc + 2] = vals[2];
        sS[hr][sc + 3] = vals[3];
    }
    __syncthreads();

    int r_i = threadIdx.x >> 5, c_i = threadIdx.x & 31;
    int g4c = col4 + c_i;
    int gc0 = g4c << 2;
    float ats = 0.f, att = 0.f, ar0s = 0.f, ar0t = 0.f;
    #pragma unroll
    for (int k = 0; k < 2; k++) {
        int grow = row0 + r_i + (k << 3);
        int i4 = (grow << 8) + g4c;
        int hr = r_i + 1 + (k << 3), sc = (c_i + 1) << 2;
        float4 sc_raw;
        sc_raw.x = sSR[hr][sc + 0];
        sc_raw.y = sSR[hr][sc + 1];
        sc_raw.z = sSR[hr][sc + 2];
        sc_raw.w = sSR[hr][sc + 3];
        ((float4*)g_s)[i4] = sc_raw;

        float4 t0;
        if (!edge) {
            #pragma unroll
            for (int j = 0; j < 4; j++) {
                float xc = sS[hr][sc + j];
                float a = (sS[hr][sc + j - 1] - xc);
                a += (sS[hr][sc + j + 1] - xc);
                a += (sS[hr - 1][sc + j] - xc);
                a += (sS[hr + 1][sc + j] - xc);
                ((float*)&t0)[j] = a * INV_DX2_;
            }
        } else {
            #pragma unroll
            for (int j = 0; j < 4; j++) {
                float xc = sS[hr][sc + j];
                float a = 0.f;
                int gc = gc0 + j;
                if (gc > 0)          a += sS[hr][sc + j - 1] - xc;
                if (gc < C_ - 1)     a += sS[hr][sc + j + 1] - xc;
                if (grow > 0)        a += sS[hr - 1][sc + j] - xc;
                if (grow < R_ - 1)   a += sS[hr + 1][sc + j] - xc;
                ((float*)&t0)[j] = a * INV_DX2_;
            }
        }
        ((float4*)g_t)[i4] = t0;
        float4 r0v = ((const float4*)g_r0)[i4];
        ats  += dot4f(t0, sc_raw);
        att  += dot4f(t0, t0);
        ar0s += dot4f(r0v, sc_raw);
        ar0t += dot4f(r0v, t0);
    }
    int slot = (it + 1) * NSLOT + (blockIdx.x & (NSLOT - 1));
    red4f(ats, att, ar0s, ar0t,
          &g_dts[slot], &g_dtt[slot], &g_dr0s[slot], &g_dr0t[slot]);
}

// ---------------- k_eff: eff per node (final x on the fly, float4) ---------
__global__ void __launch_bounds__(256) k_eff(const float* __restrict__ bed,
                                             const float* __restrict__ ob) {
    __shared__ float shs[2];
    if (threadIdx.x == 0) {
        double rho_n = rho_of(ITERS_);
        shs[0] = (float)(rho_n / (slotsum(&g_dr0v[ITERS_ * NSLOT]) + EPSD));  // al14
        shs[1] = (float)(slotsum(&g_dts[ITERS_ * NSLOT]) /
                         (slotsum(&g_dtt[ITERS_ * NSLOT]) + EPSD));           // om14
    }
    __syncthreads();
    float al = shs[0], om = shs[1];

    int i4 = blockIdx.x * blockDim.x + threadIdx.x;   // over TOT4
    float4 xv = ((const float4*)g_x )[i4];
    float4 pv = ((const float4*)g_pB)[i4];   // final p buffer (pNew of it=14)
    float4 sv = ((const float4*)g_s )[i4];
    float4 bv = ((const float4*)bed)[i4];
    float4 ov = ((const float4*)ob )[i4];
    float4 e;
    #pragma unroll
    for (int j = 0; j < 4; j++) {
        float xf = (((const float*)&xv)[j] + al * ((const float*)&pv)[j])
                 + om * ((const float*)&sv)[j];
        float pd = xf - RWG_ * ((const float*)&bv)[j];
        float o  = ((const float*)&ov)[j];
        float wp = fminf(fmaxf(pd, 0.f), o);
        ((float*)&e)[j] = o - wp;
    }
    ((float4*)g_eff)[i4] = e;
}

// ---------------- epilogue: analytic topology, eff gathered -----------------
__global__ void __launch_bounds__(256) k_out(const float4* __restrict__ cs,
                                             const float4* __restrict__ q,
                                             const int4* __restrict__ fd,
                                             float4* __restrict__ out,
                                             const int* __restrict__ dtp) {
    int i = blockIdx.x * blockDim.x + threadIdx.x;   // over L_/4
    if (i >= L_ / 4) return;
    float dtf = (float)__ldg(dtp);
    float4 c4 = cs[i];
    float4 q4 = q[i];
    int4  f4 = fd[i];
    float4 g4 = ((const float4*)g_grad)[i];
    int l0 = i << 2;
    float4 o;
    #pragma unroll
    for (int j = 0; j < 4; j++) {
        int l = l0 + j;
        int tail, head;
        if (l < HL_) {
            int r = l / (C_ - 1);
            int c = l - r * (C_ - 1);
            tail = r * C_ + c;
            head = tail + 1;
        } else {
            tail = l - HL_;
            head = tail + C_;
        }
        float el = fmaxf(0.5f * (__ldg(&g_eff[head]) + __ldg(&g_eff[tail])), 1.0f);
        float csv = ((const float*)&c4)[j];
        float melt = A_OPEN_ * ((const float*)&q4)[j] * ((const float*)&g4)[j]
                   * (float)((const int*)&f4)[j];
        float closure = C_CLOSE_ * (el * el * el) * csv;
        ((float*)&o)[j] = fmaxf(csv + (melt - closure) * dtf, 0.001f);
    }
    out[i] = o;
}

// ---------------- launch ----------------
extern "C" void kernel_launch(void* const* d_in, const int* in_sizes, int n_in,
                              void* d_out, int out_size) {
    const float* cs   = (const float*)d_in[0];
    const float* q    = (const float*)d_in[1];
    const float* bed  = (const float*)d_in[2];
    const float* ob   = (const float*)d_in[3];
    const int*   fd   = (const int*)  d_in[4];
    const int*   io   = (const int*)  d_in[5];
    // d_in[6]=head, d_in[7]=tail unused (analytic raster topology)
    const int*   dtp  = (const int*)  d_in[8];
    float* out = (float*)d_out;

    const int TB = 256;
    const int GB_L4 = (L_ / 4 + TB - 1) / TB;  // 2046
    const int GB_4  = TOT4 / TB;               // 1024
    const int GB_T  = 512;                     // 64 x 8 tiles (single wave)

    k_grad<<<GB_L4, TB>>>((const float4*)cs, (const float4*)q, (const int4*)fd);
    k_init<<<GB_4, TB>>>(io, bed);

    for (int it = 0; it < ITERS_; ++it) {
        k_A<<<GB_T, TB>>>(io, bed, it);
        k_B<<<GB_T, TB>>>(io, bed, it);
    }

    k_eff<<<GB_4, TB>>>(bed, ob);
    k_out<<<GB_L4, TB>>>((const float4*)cs, (const float4*)q, (const int4*)fd,
                         (float4*)out, dtp);
}

// round 14
// speedup vs baseline: 1.2519x; 1.2519x over previous
#include <cuda_runtime.h>

// ---------------- problem constants (raster grid 1024x1024) ----------------
#define R_  1024
#define C_  1024
#define N_  (R_ * C_)
#define HL_ (R_ * (C_ - 1))          // horizontal links = 1,047,552
#define L_  (HL_ + (R_ - 1) * C_)    // total links = 2,095,104
#define ITERS_ 15
#define NSLOT 32
#define F4ROW (C_ / 4)               // 256 float4 per row
#define TOT4  (N_ / 4)               // 262144 float4 total

#define K_FLOW_  0.0405f
#define FLOW_EXP_ 1.25f
#define A_OPEN_  1.3455e-09f
#define C_CLOSE_ 7.11e-24f
#define RWG_     9810.0f             // rho_w * g
#define INV_DX_  (1.0f / 100.0f)
#define INV_DX2_ (1.0f / (100.0f * 100.0f))

// tile: 16 rows x 32 f4 (128 floats) per block; 512 blocks; halo 1 cell
#define SROWS 18
#define SCOLS 136
#define TSLOTS (18 * 34)             // 612 haloed f4 slots

// ---------------- device scratch (static; no allocations) ----------------
__device__ __align__(16) float g_x [N_];
__device__ __align__(16) float g_r [N_];
__device__ __align__(16) float g_pA[N_];
__device__ __align__(16) float g_pB[N_];
__device__ __align__(16) float g_vA[N_];
__device__ __align__(16) float g_vB[N_];
__device__ __align__(16) float g_s [N_];
__device__ __align__(16) float g_t [N_];
__device__ __align__(16) float g_r0[N_];
__device__ __align__(16) float g_eff[N_];
__device__ __align__(16) float g_grad[L_];

// scalar slots (32 contention-spread each)
__device__ double g_rho1[NSLOT];                    // rho[1] = dot(r0,r0)
__device__ double g_dr0v[(ITERS_ + 1) * NSLOT];     // [0]=1 ; [i+1]=dot(r0,v)
__device__ double g_dts [(ITERS_ + 1) * NSLOT];     // [0]=1 ; [i+1]=dot(t,s)
__device__ double g_dtt [(ITERS_ + 1) * NSLOT];     // [0]=1 ; [i+1]=dot(t,t)
__device__ double g_dr0s[(ITERS_ + 1) * NSLOT];     // [i+1]=dot(r0,s)
__device__ double g_dr0t[(ITERS_ + 1) * NSLOT];     // [i+1]=dot(r0,t)

#define EPSD 1e-30

// ---------------- warp-parallel f64 slot reduction (lane j owns slot j) ----
__device__ __forceinline__ double wred(double v) {
    #pragma unroll
    for (int o = 16; o > 0; o >>= 1) v += __shfl_down_sync(0xffffffffu, v, o);
    return v;   // valid in lane 0
}

// ---------------- block reductions: f32 to warp level, f64 above ----------
__device__ __forceinline__ void red1f(float v, double* dst) {
    #pragma unroll
    for (int o = 16; o > 0; o >>= 1) v += __shfl_down_sync(0xffffffffu, v, o);
    __shared__ double sm1[8];
    int lane = threadIdx.x & 31, w = threadIdx.x >> 5;
    if (lane == 0) sm1[w] = (double)v;
    __syncthreads();
    if (threadIdx.x < 8) {
        double d = sm1[threadIdx.x];
        #pragma unroll
        for (int o = 4; o > 0; o >>= 1) d += __shfl_down_sync(0xffu, d, o);
        if (threadIdx.x == 0) atomicAdd(dst, d);
    }
}

__device__ __forceinline__ void red4f(float a, float b, float c, float d,
                                      double* da, double* db, double* dc, double* dd) {
    #pragma unroll
    for (int o = 16; o > 0; o >>= 1) {
        a += __shfl_down_sync(0xffffffffu, a, o);
        b += __shfl_down_sync(0xffffffffu, b, o);
        c += __shfl_down_sync(0xffffffffu, c, o);
        d += __shfl_down_sync(0xffffffffu, d, o);
    }
    __shared__ double sma[8], smb[8], smc[8], smd[8];
    int lane = threadIdx.x & 31, w = threadIdx.x >> 5;
    if (lane == 0) { sma[w] = (double)a; smb[w] = (double)b;
                     smc[w] = (double)c; smd[w] = (double)d; }
    __syncthreads();
    if (threadIdx.x < 8) {
        double a_ = sma[threadIdx.x], b_ = smb[threadIdx.x];
        double c_ = smc[threadIdx.x], d_ = smd[threadIdx.x];
        #pragma unroll
        for (int o = 4; o > 0; o >>= 1) {
            a_ += __shfl_down_sync(0xffu, a_, o);
            b_ += __shfl_down_sync(0xffu, b_, o);
            c_ += __shfl_down_sync(0xffu, c_, o);
            d_ += __shfl_down_sync(0xffu, d_, o);
        }
        if (threadIdx.x == 0) {
            atomicAdd(da, a_); atomicAdd(db, b_);
            atomicAdd(dc, c_); atomicAdd(dd, d_);
        }
    }
}

__device__ __forceinline__ float dot4f(float4 a, float4 b) {
    return a.x * b.x + a.y * b.y + a.z * b.z + a.w * b.w;
}

__device__ __forceinline__ bool is_border(int r, int c) {
    return (r == 0 || r == R_ - 1 || c == 0 || c == C_ - 1);
}

// ---------------- prologue kernel: grad (float4) + scalar-slot init --------
__device__ __forceinline__ float pow125(float s) {
    return s * sqrtf(sqrtf(s));   // s^1.25
}

__global__ void __launch_bounds__(256) k_grad(const float4* __restrict__ cs,
                                              const float4* __restrict__ q,
                                              const int4* __restrict__ fd) {
    int i = blockIdx.x * blockDim.x + threadIdx.x;   // over L_/4
    if (blockIdx.x == 0) {
        for (int j = threadIdx.x; j < NSLOT; j += 256) g_rho1[j] = 0.0;
        for (int j = threadIdx.x; j < (ITERS_ + 1) * NSLOT; j += 256) {
            double v = (j == 0) ? 1.0 : 0.0;
            g_dr0v[j] = v; g_dts[j] = v; g_dtt[j] = v;
            g_dr0s[j] = 0.0; g_dr0t[j] = 0.0;
        }
    }
    if (i < L_ / 4) {
        float4 s = cs[i];
        float4 qq = q[i];
        int4  f = fd[i];
        float4 o;
        float gx = qq.x / (K_FLOW_ * pow125(s.x)); o.x = gx * gx * (float)f.x;
        float gy = qq.y / (K_FLOW_ * pow125(s.y)); o.y = gy * gy * (float)f.y;
        float gz = qq.z / (K_FLOW_ * pow125(s.z)); o.z = gz * gz * (float)f.z;
        float gw = qq.w / (K_FLOW_ * pow125(s.w)); o.w = gw * gw * (float)f.w;
        ((float4*)g_grad)[i] = o;
    }
}

// ---------------- init: r0 = b - A(0); zero x, pA, vA (vectorized) --------
__device__ __forceinline__ float xb0v(const int* __restrict__ io,
                                      const float* __restrict__ bed, int r, int c) {
    if (is_border(r, c)) {
        int n = r * C_ + c;
        if (__ldg(&io[n]) == -1) return RWG_ * __ldg(&bed[n]);
    }
    return 0.f;
}

__global__ void __launch_bounds__(256) k_init(const int* __restrict__ io,
                                              const float* __restrict__ bed) {
    int i4 = blockIdx.x * blockDim.x + threadIdx.x;   // over TOT4
    int n = i4 << 2;
    int r = n >> 10, c0 = n & (C_ - 1);

    float4 gv  = make_float4(0.f, 0.f, 0.f, 0.f);
    float4 gvu = make_float4(0.f, 0.f, 0.f, 0.f);
    if (r < R_ - 1) gv  = ((const float4*)g_grad)[(HL_ + n) >> 2];
    if (r > 0)      gvu = ((const float4*)g_grad)[(HL_ + n - C_) >> 2];
    int hb = r * (C_ - 1);
    float ghm = (c0 > 0) ? __ldg(&g_grad[hb + c0 - 1]) : 0.f;
    float gh0 = __ldg(&g_grad[hb + c0 + 0]);
    float gh1 = __ldg(&g_grad[hb + c0 + 1]);
    float gh2 = __ldg(&g_grad[hb + c0 + 2]);
    float gh3 = (c0 + 3 < C_ - 1) ? __ldg(&g_grad[hb + c0 + 3]) : 0.f;

    float4 r0v;
    #pragma unroll
    for (int j = 0; j < 4; j++) {
        int c = c0 + j;
        float ghR = (j == 0) ? gh0 : (j == 1) ? gh1 : (j == 2) ? gh2 : gh3;
        float ghL = (j == 0) ? ghm : (j == 1) ? gh0 : (j == 2) ? gh1 : gh2;
        float gvD = ((const float*)&gv)[j];
        float gvU = ((const float*)&gvu)[j];
        float acc = 0.f;
        if (c < C_ - 1) acc += ghR;
        if (r < R_ - 1) acc += gvD;
        if (c > 0)      acc -= ghL;
        if (r > 0)      acc -= gvU;
        float b = acc * INV_DX_;
        float xc = xb0v(io, bed, r, c);
        float a = 0.f;
        if (c > 0)      a += xb0v(io, bed, r, c - 1) - xc;
        if (c < C_ - 1) a += xb0v(io, bed, r, c + 1) - xc;
        if (r > 0)      a += xb0v(io, bed, r - 1, c) - xc;
        if (r < R_ - 1) a += xb0v(io, bed, r + 1, c) - xc;
        ((float*)&r0v)[j] = b - a * INV_DX2_;
    }
    ((float4*)g_r0)[i4] = r0v;
    ((float4*)g_r )[i4] = r0v;
    float4 z = make_float4(0.f, 0.f, 0.f, 0.f);
    ((float4*)g_x )[i4] = z;
    ((float4*)g_pA)[i4] = z;
    ((float4*)g_vA)[i4] = z;
    red1f(dot4f(r0v, r0v), &g_rho1[blockIdx.x & (NSLOT - 1)]);
}

// ---------------- K_A: r_cur = s - om_p*t (it>=1) ; x += al_p*p + om_p*s ;
//    p_new = r_cur + beta*(p_old - om_p*v_old) ; v_new = A(xb(p_new)) ;
//    dot(r0, v_new) --------------------------------------------------------
__global__ void __launch_bounds__(256, 4) k_A(const int* __restrict__ io,
                                              const float* __restrict__ bed,
                                              int it) {
    int pp = it & 1;
    const float* __restrict__ pOld = pp ? g_pB : g_pA;
    const float* __restrict__ vOld = pp ? g_vB : g_vA;
    float* __restrict__ pNew = pp ? g_pA : g_pB;
    float* __restrict__ vNew = pp ? g_vA : g_vB;
    const bool first = (it == 0);

    __shared__ float sP[SROWS][SCOLS];
    __shared__ float shs[3];
    // warp-parallel scalar head: lane j owns slot j of each array
    if (threadIdx.x < 32) {
        int lane = threadIdx.x;
        double dts_c  = wred(g_dts [it * NSLOT + lane]);
        double dtt_c  = wred(g_dtt [it * NSLOT + lane]);
        double dr0v_c = wred(g_dr0v[it * NSLOT + lane]);
        double dr0s_c = wred(g_dr0s[it * NSLOT + lane]);
        double dr0t_c = wred(g_dr0t[it * NSLOT + lane]);
        double rho_p, rho_n;
        if (it == 0) {
            rho_p = 1.0;
            rho_n = wred(g_rho1[lane]);
        } else if (it == 1) {
            rho_p = wred(g_rho1[lane]);
            rho_n = 0.0;   // computed below from current-index sums
        } else {
            double dts_p  = wred(g_dts [(it - 1) * NSLOT + lane]);
            double dtt_p  = wred(g_dtt [(it - 1) * NSLOT + lane]);
            double dr0s_p = wred(g_dr0s[(it - 1) * NSLOT + lane]);
            double dr0t_p = wred(g_dr0t[(it - 1) * NSLOT + lane]);
            double om_pp = dts_p / (dtt_p + EPSD);
            rho_p = dr0s_p - om_pp * dr0t_p;
            rho_n = 0.0;
        }
        if (lane == 0) {
            double om_p = dts_c / (dtt_c + EPSD);
            double al_p = rho_p / (dr0v_c + EPSD);
            if (it != 0) rho_n = dr0s_c - om_p * dr0t_c;
            shs[0] = (float)((rho_n / (rho_p + EPSD)) * (al_p / (om_p + EPSD)));
            shs[1] = (float)om_p;
            shs[2] = (float)al_p;
        }
    }
    __syncthreads();
    float beta = shs[0], om = shs[1], al = shs[2];

    int b = blockIdx.x;                  // 512 blocks: 64 tile-rows x 8 tile-cols
    int tx = b & 7, ty = b >> 3;
    int row0 = ty << 4, col4 = tx << 5;
    bool edge = (ty == 0) || (ty == 63) || (tx == 0) || (tx == 7);

    // fill smem with xb-substituted p_new over haloed region
    for (int slot = threadIdx.x; slot < TSLOTS; slot += 256) {
        int hr = slot / 34, hc = slot - hr * 34;
        int grow = row0 - 1 + hr;
        int g4c  = col4 - 1 + hc;
        if ((unsigned)grow > (unsigned)(R_ - 1) ||
            (unsigned)g4c  > (unsigned)(F4ROW - 1)) continue;
        int i4 = (grow << 8) + g4c;
        float4 pv = ((const float4*)pOld)[i4];
        float4 vv = ((const float4*)vOld)[i4];
        float4 rn;
        if (first) {
            rn = ((const float4*)g_r)[i4];
        } else {
            float4 sv = ((const float4*)g_s)[i4];
            float4 tv = ((const float4*)g_t)[i4];
            rn.x = sv.x - om * tv.x;  rn.y = sv.y - om * tv.y;
            rn.z = sv.z - om * tv.z;  rn.w = sv.w - om * tv.w;
        }
        float vals[4];
        vals[0] = rn.x + beta * (pv.x - om * vv.x);
        vals[1] = rn.y + beta * (pv.y - om * vv.y);
        vals[2] = rn.z + beta * (pv.z - om * vv.z);
        vals[3] = rn.w + beta * (pv.w - om * vv.w);
        if (edge) {
            int nb = (grow << 10) + (g4c << 2);
            #pragma unroll
            for (int j = 0; j < 4; j++) {
                int gc = (g4c << 2) + j;
                if (is_border(grow, gc) && __ldg(&io[nb + j]) == -1)
                    vals[j] = RWG_ * __ldg(&bed[nb + j]);
            }
        }
        int sc = hc << 2;
        sP[hr][sc + 0] = vals[0];
        sP[hr][sc + 1] = vals[1];
        sP[hr][sc + 2] = vals[2];
        sP[hr][sc + 3] = vals[3];
    }
    __syncthreads();

    // two output rows per thread: r_i and r_i + 8
    int r_i = threadIdx.x >> 5, c_i = threadIdx.x & 31;
    int g4c = col4 + c_i;
    int gc0 = g4c << 2;
    float acc = 0.f;
    #pragma unroll
    for (int k = 0; k < 2; k++) {
        int grow = row0 + r_i + (k << 3);
        int i4 = (grow << 8) + g4c;
        float4 pv = ((const float4*)pOld)[i4];
        float4 vv = ((const float4*)vOld)[i4];
        float4 rn;
        if (first) {
            rn = ((const float4*)g_r)[i4];
        } else {
            float4 sv = ((const float4*)g_s)[i4];
            float4 tv = ((const float4*)g_t)[i4];
            rn.x = sv.x - om * tv.x;  rn.y = sv.y - om * tv.y;
            rn.z = sv.z - om * tv.z;  rn.w = sv.w - om * tv.w;
            ((float4*)g_r)[i4] = rn;
            // deferred x update of iteration it-1 (identical expression)
            float4 xv = ((const float4*)g_x)[i4];
            float4 xn;
            xn.x = (xv.x + al * pv.x) + om * sv.x;
            xn.y = (xv.y + al * pv.y) + om * sv.y;
            xn.z = (xv.z + al * pv.z) + om * sv.z;
            xn.w = (xv.w + al * pv.w) + om * sv.w;
            ((float4*)g_x)[i4] = xn;
        }
        float4 pn;
        pn.x = rn.x + beta * (pv.x - om * vv.x);
        pn.y = rn.y + beta * (pv.y - om * vv.y);
        pn.z = rn.z + beta * (pv.z - om * vv.z);
        pn.w = rn.w + beta * (pv.w - om * vv.w);
        ((float4*)pNew)[i4] = pn;

        int hr = r_i + 1 + (k << 3), sc = (c_i + 1) << 2;
        float4 vout;
        if (!edge) {
            #pragma unroll
            for (int j = 0; j < 4; j++) {
                float xc = sP[hr][sc + j];
                float a = (sP[hr][sc + j - 1] - xc);
                a += (sP[hr][sc + j + 1] - xc);
                a += (sP[hr - 1][sc + j] - xc);
                a += (sP[hr + 1][sc + j] - xc);
                ((float*)&vout)[j] = a * INV_DX2_;
            }
        } else {
            #pragma unroll
            for (int j = 0; j < 4; j++) {
                float xc = sP[hr][sc + j];
                float a = 0.f;
                int gc = gc0 + j;
                if (gc > 0)          a += sP[hr][sc + j - 1] - xc;
                if (gc < C_ - 1)     a += sP[hr][sc + j + 1] - xc;
                if (grow > 0)        a += sP[hr - 1][sc + j] - xc;
                if (grow < R_ - 1)   a += sP[hr + 1][sc + j] - xc;
                ((float*)&vout)[j] = a * INV_DX2_;
            }
        }
        ((float4*)vNew)[i4] = vout;
        acc += dot4f(((const float4*)g_r0)[i4], vout);
    }
    red1f(acc, &g_dr0v[(it + 1) * NSLOT + (blockIdx.x & (NSLOT - 1))]);
}

// ---------------- K_B: s = r - al*v ; t = A(xb(s)) ;
//    dots (t,s),(t,t),(r0,s),(r0,t) -----------------------------------------
__global__ void __launch_bounds__(256, 4) k_B(const int* __restrict__ io,
                                              const float* __restrict__ bed,
                                              int it) {
    int pp = it & 1;
    const float* __restrict__ v = pp ? g_vA : g_vB;   // v_new of this iter

    __shared__ float sS[SROWS][SCOLS];
    __shared__ float shs[1];
    if (threadIdx.x < 32) {
        int lane = threadIdx.x;
        double dr0v_n = wred(g_dr0v[(it + 1) * NSLOT + lane]);
        double rho_n;
        if (it == 0) {
            rho_n = wred(g_rho1[lane]);
        } else {
            double dts_c  = wred(g_dts [it * NSLOT + lane]);
            double dtt_c  = wred(g_dtt [it * NSLOT + lane]);
            double dr0s_c = wred(g_dr0s[it * NSLOT + lane]);
            double dr0t_c = wred(g_dr0t[it * NSLOT + lane]);
            double om_p = dts_c / (dtt_c + EPSD);
            rho_n = dr0s_c - om_p * dr0t_c;
        }
        if (lane == 0)
            shs[0] = (float)(rho_n / (dr0v_n + EPSD));
    }
    __syncthreads();
    float al = shs[0];

    int b = blockIdx.x;
    int tx = b & 7, ty = b >> 3;
    int row0 = ty << 4, col4 = tx << 5;
    bool edge = (ty == 0) || (ty == 63) || (tx == 0) || (tx == 7);

    for (int slot = threadIdx.x; slot < TSLOTS; slot += 256) {
        int hr = slot / 34, hc = slot - hr * 34;
        int grow = row0 - 1 + hr;
        int g4c  = col4 - 1 + hc;
        if ((unsigned)grow > (unsigned)(R_ - 1) ||
            (unsigned)g4c  > (unsigned)(F4ROW - 1)) continue;
        int i4 = (grow << 8) + g4c;
        float4 rv = ((const float4*)g_r)[i4];
        float4 vv = ((const float4*)v)[i4];
        float vals[4];
        vals[0] = rv.x - al * vv.x;
        vals[1] = rv.y - al * vv.y;
        vals[2] = rv.z - al * vv.z;
        vals[3] = rv.w - al * vv.w;
        if (edge) {
            int nb = (grow << 10) + (g4c << 2);
            #pragma unroll
            for (int j = 0; j < 4; j++) {
                int gc = (g4c << 2) + j;
                if (is_border(grow, gc) && __ldg(&io[nb + j]) == -1)
                    vals[j] = RWG_ * __ldg(&bed[nb + j]);
            }
        }
        int sc = hc << 2;
        sS[hr][sc + 0] = vals[0];
        sS[hr][sc + 1] = vals[1];
        sS[hr][sc + 2] = vals[2];
        sS[hr][sc + 3] = vals[3];
    }
    __syncthreads();

    int r_i = threadIdx.x >> 5, c_i = threadIdx.x & 31;
    int g4c = col4 + c_i;
    int gc0 = g4c << 2;
    float ats = 0.f, att = 0.f, ar0s = 0.f, ar0t = 0.f;
    #pragma unroll
    for (int k = 0; k < 2; k++) {
        int grow = row0 + r_i + (k << 3);
        int i4 = (grow << 8) + g4c;
        float4 rv = ((const float4*)g_r)[i4];
        float4 vv = ((const float4*)v)[i4];
        float4 sc_raw;
        sc_raw.x = rv.x - al * vv.x;
        sc_raw.y = rv.y - al * vv.y;
        sc_raw.z = rv.z - al * vv.z;
        sc_raw.w = rv.w - al * vv.w;
        ((float4*)g_s)[i4] = sc_raw;

        int hr = r_i + 1 + (k << 3), sc = (c_i + 1) << 2;
        float4 t0;
        if (!edge) {
            #pragma unroll
            for (int j = 0; j < 4; j++) {
                float xc = sS[hr][sc + j];
                float a = (sS[hr][sc + j - 1] - xc);
                a += (sS[hr][sc + j + 1] - xc);
                a += (sS[hr - 1][sc + j] - xc);
                a += (sS[hr + 1][sc + j] - xc);
                ((float*)&t0)[j] = a * INV_DX2_;
            }
        } else {
            #pragma unroll
            for (int j = 0; j < 4; j++) {
                float xc = sS[hr][sc + j];
                float a = 0.f;
                int gc = gc0 + j;
                if (gc > 0)          a += sS[hr][sc + j - 1] - xc;
                if (gc < C_ - 1)     a += sS[hr][sc + j + 1] - xc;
                if (grow > 0)        a += sS[hr - 1][sc + j] - xc;
                if (grow < R_ - 1)   a += sS[hr + 1][sc + j] - xc;
                ((float*)&t0)[j] = a * INV_DX2_;
            }
        }
        ((float4*)g_t)[i4] = t0;
        float4 r0v = ((const float4*)g_r0)[i4];
        ats  += dot4f(t0, sc_raw);
        att  += dot4f(t0, t0);
        ar0s += dot4f(r0v, sc_raw);
        ar0t += dot4f(r0v, t0);
    }
    int slot = (it + 1) * NSLOT + (blockIdx.x & (NSLOT - 1));
    red4f(ats, att, ar0s, ar0t,
          &g_dts[slot], &g_dtt[slot], &g_dr0s[slot], &g_dr0t[slot]);
}

// ---------------- k_eff: eff per node (final x on the fly, float4) ---------
__global__ void __launch_bounds__(256) k_eff(const float* __restrict__ bed,
                                             const float* __restrict__ ob) {
    __shared__ float shs[2];
    if (threadIdx.x < 32) {
        int lane = threadIdx.x;
        // rho_of(15) from index 14; al14 = rho/dr0v[15]; om14 = dts[15]/dtt[15]
        double dts14  = wred(g_dts [(ITERS_ - 1) * NSLOT + lane]);
        double dtt14  = wred(g_dtt [(ITERS_ - 1) * NSLOT + lane]);
        double dr0s14 = wred(g_dr0s[(ITERS_ - 1) * NSLOT + lane]);
        double dr0t14 = wred(g_dr0t[(ITERS_ - 1) * NSLOT + lane]);
        double dr0v15 = wred(g_dr0v[ITERS_ * NSLOT + lane]);
        double dts15  = wred(g_dts [ITERS_ * NSLOT + lane]);
        double dtt15  = wred(g_dtt [ITERS_ * NSLOT + lane]);
        if (lane == 0) {
            double om_p = dts14 / (dtt14 + EPSD);
            double rho_n = dr0s14 - om_p * dr0t14;
            shs[0] = (float)(rho_n / (dr0v15 + EPSD));       // al14
            shs[1] = (float)(dts15 / (dtt15 + EPSD));        // om14
        }
    }
    __syncthreads();
    float al = shs[0], om = shs[1];

    int i4 = blockIdx.x * blockDim.x + threadIdx.x;   // over TOT4
    float4 xv = ((const float4*)g_x )[i4];
    float4 pv = ((const float4*)g_pB)[i4];   // final p buffer (pNew of it=14)
    float4 sv = ((const float4*)g_s )[i4];
    float4 bv = ((const float4*)bed)[i4];
    float4 ov = ((const float4*)ob )[i4];
    float4 e;
    #pragma unroll
    for (int j = 0; j < 4; j++) {
        float xf = (((const float*)&xv)[j] + al * ((const float*)&pv)[j])
                 + om * ((const float*)&sv)[j];
        float pd = xf - RWG_ * ((const float*)&bv)[j];
        float o  = ((const float*)&ov)[j];
        float wp = fminf(fmaxf(pd, 0.f), o);
        ((float*)&e)[j] = o - wp;
    }
    ((float4*)g_eff)[i4] = e;
}

// ---------------- epilogue: analytic topology, eff gathered -----------------
__global__ void __launch_bounds__(256) k_out(const float4* __restrict__ cs,
                                             const float4* __restrict__ q,
                                             const int4* __restrict__ fd,
                                             float4* __restrict__ out,
                                             const int* __restrict__ dtp) {
    int i = blockIdx.x * blockDim.x + threadIdx.x;   // over L_/4
    if (i >= L_ / 4) return;
    float dtf = (float)__ldg(dtp);
    float4 c4 = cs[i];
    float4 q4 = q[i];
    int4  f4 = fd[i];
    float4 g4 = ((const float4*)g_grad)[i];
    int l0 = i << 2;
    float4 o;
    #pragma unroll
    for (int j = 0; j < 4; j++) {
        int l = l0 + j;
        int tail, head;
        if (l < HL_) {
            int r = l / (C_ - 1);
            int c = l - r * (C_ - 1);
            tail = r * C_ + c;
            head = tail + 1;
        } else {
            tail = l - HL_;
            head = tail + C_;
        }
        float el = fmaxf(0.5f * (__ldg(&g_eff[head]) + __ldg(&g_eff[tail])), 1.0f);
        float csv = ((const float*)&c4)[j];
        float melt = A_OPEN_ * ((const float*)&q4)[j] * ((const float*)&g4)[j]
                   * (float)((const int*)&f4)[j];
        float closure = C_CLOSE_ * (el * el * el) * csv;
        ((float*)&o)[j] = fmaxf(csv + (melt - closure) * dtf, 0.001f);
    }
    out[i] = o;
}

// ---------------- launch ----------------
extern "C" void kernel_launch(void* const* d_in, const int* in_sizes, int n_in,
                              void* d_out, int out_size) {
    const float* cs   = (const float*)d_in[0];
    const float* q    = (const float*)d_in[1];
    const float* bed  = (const float*)d_in[2];
    const float* ob   = (const float*)d_in[3];
    const int*   fd   = (const int*)  d_in[4];
    const int*   io   = (const int*)  d_in[5];
    // d_in[6]=head, d_in[7]=tail unused (analytic raster topology)
    const int*   dtp  = (const int*)  d_in[8];
    float* out = (float*)d_out;

    const int TB = 256;
    const int GB_L4 = (L_ / 4 + TB - 1) / TB;  // 2046
    const int GB_4  = TOT4 / TB;               // 1024
    const int GB_T  = 512;                     // 64 x 8 tiles (single wave)

    k_grad<<<GB_L4, TB>>>((const float4*)cs, (const float4*)q, (const int4*)fd);
    k_init<<<GB_4, TB>>>(io, bed);

    for (int it = 0; it < ITERS_; ++it) {
        k_A<<<GB_T, TB>>>(io, bed, it);
        k_B<<<GB_T, TB>>>(io, bed, it);
    }

    k_eff<<<GB_4, TB>>>(bed, ob);
    k_out<<<GB_L4, TB>>>((const float4*)cs, (const float4*)q, (const int4*)fd,
                         (float4*)out, dtp);
}

// round 16
// speedup vs baseline: 1.2520x; 1.0001x over previous
#include <cuda_runtime.h>

// ---------------- problem constants (raster grid 1024x1024) ----------------
#define R_  1024
#define C_  1024
#define N_  (R_ * C_)
#define HL_ (R_ * (C_ - 1))          // horizontal links = 1,047,552
#define L_  (HL_ + (R_ - 1) * C_)    // total links = 2,095,104
#define ITERS_ 15
#define NSLOT 32
#define F4ROW (C_ / 4)               // 256 float4 per row
#define TOT4  (N_ / 4)               // 262144 float4 total

#define K_FLOW_  0.0405f
#define FLOW_EXP_ 1.25f
#define A_OPEN_  1.3455e-09f
#define C_CLOSE_ 7.11e-24f
#define RWG_     9810.0f             // rho_w * g
#define INV_DX_  (1.0f / 100.0f)
#define INV_DX2_ (1.0f / (100.0f * 100.0f))

// tile: 16 rows x 32 f4 (128 floats) per block; 512 blocks; halo 1 cell
#define SROWS 18
#define SCOLS 136
#define TSLOTS (18 * 34)             // 612 haloed f4 slots

// ---------------- device scratch (static; no allocations) ----------------
__device__ __align__(16) float g_x [N_];
__device__ __align__(16) float g_r [N_];
__device__ __align__(16) float g_pA[N_];
__device__ __align__(16) float g_pB[N_];
__device__ __align__(16) float g_vA[N_];
__device__ __align__(16) float g_vB[N_];
__device__ __align__(16) float g_s [N_];
__device__ __align__(16) float g_t [N_];
__device__ __align__(16) float g_r0[N_];
__device__ __align__(16) float g_eff[N_];
__device__ __align__(16) float g_grad[L_];

// scalar slots (32 contention-spread each)
__device__ double g_rho1[NSLOT];                    // rho[1] = dot(r0,r0)
__device__ double g_dr0v[(ITERS_ + 1) * NSLOT];     // [0]=1 ; [i+1]=dot(r0,v)
__device__ double g_dts [(ITERS_ + 1) * NSLOT];     // [0]=1 ; [i+1]=dot(t,s)
__device__ double g_dtt [(ITERS_ + 1) * NSLOT];     // [0]=1 ; [i+1]=dot(t,t)
__device__ double g_dr0s[(ITERS_ + 1) * NSLOT];     // [i+1]=dot(r0,s)
__device__ double g_dr0t[(ITERS_ + 1) * NSLOT];     // [i+1]=dot(r0,t)

#define EPSD 1e-30

// ---------------- warp-parallel f64 slot reduction (lane j owns slot j) ----
__device__ __forceinline__ double wred(double v) {
    #pragma unroll
    for (int o = 16; o > 0; o >>= 1) v += __shfl_down_sync(0xffffffffu, v, o);
    return v;   // valid in lane 0
}

// ---------------- block reductions: f32 to warp level, f64 above ----------
__device__ __forceinline__ void red1f(float v, double* dst) {
    #pragma unroll
    for (int o = 16; o > 0; o >>= 1) v += __shfl_down_sync(0xffffffffu, v, o);
    __shared__ double sm1[8];
    int lane = threadIdx.x & 31, w = threadIdx.x >> 5;
    if (lane == 0) sm1[w] = (double)v;
    __syncthreads();
    if (threadIdx.x < 8) {
        double d = sm1[threadIdx.x];
        #pragma unroll
        for (int o = 4; o > 0; o >>= 1) d += __shfl_down_sync(0xffu, d, o);
        if (threadIdx.x == 0) atomicAdd(dst, d);
    }
}

__device__ __forceinline__ void red4f(float a, float b, float c, float d,
                                      double* da, double* db, double* dc, double* dd) {
    #pragma unroll
    for (int o = 16; o > 0; o >>= 1) {
        a += __shfl_down_sync(0xffffffffu, a, o);
        b += __shfl_down_sync(0xffffffffu, b, o);
        c += __shfl_down_sync(0xffffffffu, c, o);
        d += __shfl_down_sync(0xffffffffu, d, o);
    }
    __shared__ double sma[8], smb[8], smc[8], smd[8];
    int lane = threadIdx.x & 31, w = threadIdx.x >> 5;
    if (lane == 0) { sma[w] = (double)a; smb[w] = (double)b;
                     smc[w] = (double)c; smd[w] = (double)d; }
    __syncthreads();
    if (threadIdx.x < 8) {
        double a_ = sma[threadIdx.x], b_ = smb[threadIdx.x];
        double c_ = smc[threadIdx.x], d_ = smd[threadIdx.x];
        #pragma unroll
        for (int o = 4; o > 0; o >>= 1) {
            a_ += __shfl_down_sync(0xffu, a_, o);
            b_ += __shfl_down_sync(0xffu, b_, o);
            c_ += __shfl_down_sync(0xffu, c_, o);
            d_ += __shfl_down_sync(0xffu, d_, o);
        }
        if (threadIdx.x == 0) {
            atomicAdd(da, a_); atomicAdd(db, b_);
            atomicAdd(dc, c_); atomicAdd(dd, d_);
        }
    }
}

__device__ __forceinline__ float dot4f(float4 a, float4 b) {
    return a.x * b.x + a.y * b.y + a.z * b.z + a.w * b.w;
}

__device__ __forceinline__ bool is_border(int r, int c) {
    return (r == 0 || r == R_ - 1 || c == 0 || c == C_ - 1);
}

// ---------------- prologue kernel: grad (float4) + scalar-slot init --------
__device__ __forceinline__ float pow125(float s) {
    return s * sqrtf(sqrtf(s));   // s^1.25
}

__global__ void __launch_bounds__(256) k_grad(const float4* __restrict__ cs,
                                              const float4* __restrict__ q,
                                              const int4* __restrict__ fd) {
    int i = blockIdx.x * blockDim.x + threadIdx.x;   // over L_/4
    if (blockIdx.x == 0) {
        for (int j = threadIdx.x; j < NSLOT; j += 256) g_rho1[j] = 0.0;
        for (int j = threadIdx.x; j < (ITERS_ + 1) * NSLOT; j += 256) {
            double v = (j == 0) ? 1.0 : 0.0;
            g_dr0v[j] = v; g_dts[j] = v; g_dtt[j] = v;
            g_dr0s[j] = 0.0; g_dr0t[j] = 0.0;
        }
    }
    if (i < L_ / 4) {
        float4 s = cs[i];
        float4 qq = q[i];
        int4  f = fd[i];
        float4 o;
        float gx = qq.x / (K_FLOW_ * pow125(s.x)); o.x = gx * gx * (float)f.x;
        float gy = qq.y / (K_FLOW_ * pow125(s.y)); o.y = gy * gy * (float)f.y;
        float gz = qq.z / (K_FLOW_ * pow125(s.z)); o.z = gz * gz * (float)f.z;
        float gw = qq.w / (K_FLOW_ * pow125(s.w)); o.w = gw * gw * (float)f.w;
        ((float4*)g_grad)[i] = o;
    }
}

// ---------------- init: r0 = b - A(0); zero x, pA, vA (vectorized) --------
__device__ __forceinline__ float xb0v(const int* __restrict__ io,
                                      const float* __restrict__ bed, int r, int c) {
    if (is_border(r, c)) {
        int n = r * C_ + c;
        if (__ldg(&io[n]) == -1) return RWG_ * __ldg(&bed[n]);
    }
    return 0.f;
}

__global__ void __launch_bounds__(256) k_init(const int* __restrict__ io,
                                              const float* __restrict__ bed) {
    int i4 = blockIdx.x * blockDim.x + threadIdx.x;   // over TOT4
    int n = i4 << 2;
    int r = n >> 10, c0 = n & (C_ - 1);

    float4 gv  = make_float4(0.f, 0.f, 0.f, 0.f);
    float4 gvu = make_float4(0.f, 0.f, 0.f, 0.f);
    if (r < R_ - 1) gv  = ((const float4*)g_grad)[(HL_ + n) >> 2];
    if (r > 0)      gvu = ((const float4*)g_grad)[(HL_ + n - C_) >> 2];
    int hb = r * (C_ - 1);
    float ghm = (c0 > 0) ? __ldg(&g_grad[hb + c0 - 1]) : 0.f;
    float gh0 = __ldg(&g_grad[hb + c0 + 0]);
    float gh1 = __ldg(&g_grad[hb + c0 + 1]);
    float gh2 = __ldg(&g_grad[hb + c0 + 2]);
    float gh3 = (c0 + 3 < C_ - 1) ? __ldg(&g_grad[hb + c0 + 3]) : 0.f;

    float4 r0v;
    #pragma unroll
    for (int j = 0; j < 4; j++) {
        int c = c0 + j;
        float ghR = (j == 0) ? gh0 : (j == 1) ? gh1 : (j == 2) ? gh2 : gh3;
        float ghL = (j == 0) ? ghm : (j == 1) ? gh0 : (j == 2) ? gh1 : gh2;
        float gvD = ((const float*)&gv)[j];
        float gvU = ((const float*)&gvu)[j];
        float acc = 0.f;
        if (c < C_ - 1) acc += ghR;
        if (r < R_ - 1) acc += gvD;
        if (c > 0)      acc -= ghL;
        if (r > 0)      acc -= gvU;
        float b = acc * INV_DX_;
        float xc = xb0v(io, bed, r, c);
        float a = 0.f;
        if (c > 0)      a += xb0v(io, bed, r, c - 1) - xc;
        if (c < C_ - 1) a += xb0v(io, bed, r, c + 1) - xc;
        if (r > 0)      a += xb0v(io, bed, r - 1, c) - xc;
        if (r < R_ - 1) a += xb0v(io, bed, r + 1, c) - xc;
        ((float*)&r0v)[j] = b - a * INV_DX2_;
    }
    ((float4*)g_r0)[i4] = r0v;
    ((float4*)g_r )[i4] = r0v;
    float4 z = make_float4(0.f, 0.f, 0.f, 0.f);
    ((float4*)g_x )[i4] = z;
    ((float4*)g_pA)[i4] = z;
    ((float4*)g_vA)[i4] = z;
    red1f(dot4f(r0v, r0v), &g_rho1[blockIdx.x & (NSLOT - 1)]);
}

// ---------------- K_A: r_cur = s - om_p*t (it>=1) ; x += al_p*p + om_p*s ;
//    p_new = r_cur + beta*(p_old - om_p*v_old) ; v_new = A(xb(p_new)) ;
//    dot(r0, v_new) --------------------------------------------------------
__global__ void __launch_bounds__(256, 4) k_A(const int* __restrict__ io,
                                              const float* __restrict__ bed,
                                              int it) {
    int pp = it & 1;
    const float* __restrict__ pOld = pp ? g_pB : g_pA;
    const float* __restrict__ vOld = pp ? g_vB : g_vA;
    float* __restrict__ pNew = pp ? g_pA : g_pB;
    float* __restrict__ vNew = pp ? g_vA : g_vB;
    const bool first = (it == 0);

    __shared__ float sP[SROWS][SCOLS];
    __shared__ float shs[3];
    // warp-parallel scalar head: lane j owns slot j of each array
    if (threadIdx.x < 32) {
        int lane = threadIdx.x;
        double dts_c  = wred(g_dts [it * NSLOT + lane]);
        double dtt_c  = wred(g_dtt [it * NSLOT + lane]);
        double dr0v_c = wred(g_dr0v[it * NSLOT + lane]);
        double dr0s_c = wred(g_dr0s[it * NSLOT + lane]);
        double dr0t_c = wred(g_dr0t[it * NSLOT + lane]);
        double rho_p, rho_n;
        if (it == 0) {
            rho_p = 1.0;
            rho_n = wred(g_rho1[lane]);
        } else if (it == 1) {
            rho_p = wred(g_rho1[lane]);
            rho_n = 0.0;   // computed below from current-index sums
        } else {
            double dts_p  = wred(g_dts [(it - 1) * NSLOT + lane]);
            double dtt_p  = wred(g_dtt [(it - 1) * NSLOT + lane]);
            double dr0s_p = wred(g_dr0s[(it - 1) * NSLOT + lane]);
            double dr0t_p = wred(g_dr0t[(it - 1) * NSLOT + lane]);
            double om_pp = dts_p / (dtt_p + EPSD);
            rho_p = dr0s_p - om_pp * dr0t_p;
            rho_n = 0.0;
        }
        if (lane == 0) {
            double om_p = dts_c / (dtt_c + EPSD);
            double al_p = rho_p / (dr0v_c + EPSD);
            if (it != 0) rho_n = dr0s_c - om_p * dr0t_c;
            shs[0] = (float)((rho_n / (rho_p + EPSD)) * (al_p / (om_p + EPSD)));
            shs[1] = (float)om_p;
            shs[2] = (float)al_p;
        }
    }
    __syncthreads();
    float beta = shs[0], om = shs[1], al = shs[2];

    int b = blockIdx.x;                  // 512 blocks: 64 tile-rows x 8 tile-cols
    int tx = b & 7, ty = b >> 3;
    int row0 = ty << 4, col4 = tx << 5;
    bool edge = (ty == 0) || (ty == 63) || (tx == 0) || (tx == 7);

    // fill smem with xb-substituted p_new over haloed region
    for (int slot = threadIdx.x; slot < TSLOTS; slot += 256) {
        int hr = slot / 34, hc = slot - hr * 34;
        int grow = row0 - 1 + hr;
        int g4c  = col4 - 1 + hc;
        if ((unsigned)grow > (unsigned)(R_ - 1) ||
            (unsigned)g4c  > (unsigned)(F4ROW - 1)) continue;
        int i4 = (grow << 8) + g4c;
        float4 pv = ((const float4*)pOld)[i4];
        float4 vv = ((const float4*)vOld)[i4];
        float4 rn;
        if (first) {
            rn = ((const float4*)g_r)[i4];
        } else {
            float4 sv = ((const float4*)g_s)[i4];
            float4 tv = ((const float4*)g_t)[i4];
            rn.x = sv.x - om * tv.x;  rn.y = sv.y - om * tv.y;
            rn.z = sv.z - om * tv.z;  rn.w = sv.w - om * tv.w;
        }
        float vals[4];
        vals[0] = rn.x + beta * (pv.x - om * vv.x);
        vals[1] = rn.y + beta * (pv.y - om * vv.y);
        vals[2] = rn.z + beta * (pv.z - om * vv.z);
        vals[3] = rn.w + beta * (pv.w - om * vv.w);
        if (edge) {
            int nb = (grow << 10) + (g4c << 2);
            #pragma unroll
            for (int j = 0; j < 4; j++) {
                int gc = (g4c << 2) + j;
                if (is_border(grow, gc) && __ldg(&io[nb + j]) == -1)
                    vals[j] = RWG_ * __ldg(&bed[nb + j]);
            }
        }
        int sc = hc << 2;
        sP[hr][sc + 0] = vals[0];
        sP[hr][sc + 1] = vals[1];
        sP[hr][sc + 2] = vals[2];
        sP[hr][sc + 3] = vals[3];
    }
    __syncthreads();

    // two output rows per thread: r_i and r_i + 8
    int r_i = threadIdx.x >> 5, c_i = threadIdx.x & 31;
    int g4c = col4 + c_i;
    int gc0 = g4c << 2;
    float acc = 0.f;
    #pragma unroll
    for (int k = 0; k < 2; k++) {
        int grow = row0 + r_i + (k << 3);
        int i4 = (grow << 8) + g4c;
        float4 pv = ((const float4*)pOld)[i4];
        float4 vv = ((const float4*)vOld)[i4];
        float4 rn;
        if (first) {
            rn = ((const float4*)g_r)[i4];
        } else {
            float4 sv = ((const float4*)g_s)[i4];
            float4 tv = ((const float4*)g_t)[i4];
            rn.x = sv.x - om * tv.x;  rn.y = sv.y - om * tv.y;
            rn.z = sv.z - om * tv.z;  rn.w = sv.w - om * tv.w;
            ((float4*)g_r)[i4] = rn;
            // deferred x update of iteration it-1 (identical expression)
            float4 xv = ((const float4*)g_x)[i4];
            float4 xn;
            xn.x = (xv.x + al * pv.x) + om * sv.x;
            xn.y = (xv.y + al * pv.y) + om * sv.y;
            xn.z = (xv.z + al * pv.z) + om * sv.z;
            xn.w = (xv.w + al * pv.w) + om * sv.w;
            ((float4*)g_x)[i4] = xn;
        }
        float4 pn;
        pn.x = rn.x + beta * (pv.x - om * vv.x);
        pn.y = rn.y + beta * (pv.y - om * vv.y);
        pn.z = rn.z + beta * (pv.z - om * vv.z);
        pn.w = rn.w + beta * (pv.w - om * vv.w);
        ((float4*)pNew)[i4] = pn;

        int hr = r_i + 1 + (k << 3), sc = (c_i + 1) << 2;
        float4 vout;
        if (!edge) {
            #pragma unroll
            for (int j = 0; j < 4; j++) {
                float xc = sP[hr][sc + j];
                float a = (sP[hr][sc + j - 1] - xc);
                a += (sP[hr][sc + j + 1] - xc);
                a += (sP[hr - 1][sc + j] - xc);
                a += (sP[hr + 1][sc + j] - xc);
                ((float*)&vout)[j] = a * INV_DX2_;
            }
        } else {
            #pragma unroll
            for (int j = 0; j < 4; j++) {
                float xc = sP[hr][sc + j];
                float a = 0.f;
                int gc = gc0 + j;
                if (gc > 0)          a += sP[hr][sc + j - 1] - xc;
                if (gc < C_ - 1)     a += sP[hr][sc + j + 1] - xc;
                if (grow > 0)        a += sP[hr - 1][sc + j] - xc;
                if (grow < R_ - 1)   a += sP[hr + 1][sc + j] - xc;
                ((float*)&vout)[j] = a * INV_DX2_;
            }
        }
        ((float4*)vNew)[i4] = vout;
        acc += dot4f(((const float4*)g_r0)[i4], vout);
    }
    red1f(acc, &g_dr0v[(it + 1) * NSLOT + (blockIdx.x & (NSLOT - 1))]);
}

// ---------------- K_B: s = r - al*v ; t = A(xb(s)) ;
//    dots (t,s),(t,t),(r0,s),(r0,t) -----------------------------------------
__global__ void __launch_bounds__(256, 4) k_B(const int* __restrict__ io,
                                              const float* __restrict__ bed,
                                              int it) {
    int pp = it & 1;
    const float* __restrict__ v = pp ? g_vA : g_vB;   // v_new of this iter

    __shared__ float sS[SROWS][SCOLS];
    __shared__ float shs[1];
    if (threadIdx.x < 32) {
        int lane = threadIdx.x;
        double dr0v_n = wred(g_dr0v[(it + 1) * NSLOT + lane]);
        double rho_n;
        if (it == 0) {
            rho_n = wred(g_rho1[lane]);
        } else {
            double dts_c  = wred(g_dts [it * NSLOT + lane]);
            double dtt_c  = wred(g_dtt [it * NSLOT + lane]);
            double dr0s_c = wred(g_dr0s[it * NSLOT + lane]);
            double dr0t_c = wred(g_dr0t[it * NSLOT + lane]);
            double om_p = dts_c / (dtt_c + EPSD);
            rho_n = dr0s_c - om_p * dr0t_c;
        }
        if (lane == 0)
            shs[0] = (float)(rho_n / (dr0v_n + EPSD));
    }
    __syncthreads();
    float al = shs[0];

    int b = blockIdx.x;
    int tx = b & 7, ty = b >> 3;
    int row0 = ty << 4, col4 = tx << 5;
    bool edge = (ty == 0) || (ty == 63) || (tx == 0) || (tx == 7);

    for (int slot = threadIdx.x; slot < TSLOTS; slot += 256) {
        int hr = slot / 34, hc = slot - hr * 34;
        int grow = row0 - 1 + hr;
        int g4c  = col4 - 1 + hc;
        if ((unsigned)grow > (unsigned)(R_ - 1) ||
            (unsigned)g4c  > (unsigned)(F4ROW - 1)) continue;
        int i4 = (grow << 8) + g4c;
        float4 rv = ((const float4*)g_r)[i4];
        float4 vv = ((const float4*)v)[i4];
        float vals[4];
        vals[0] = rv.x - al * vv.x;
        vals[1] = rv.y - al * vv.y;
        vals[2] = rv.z - al * vv.z;
        vals[3] = rv.w - al * vv.w;
        if (edge) {
            int nb = (grow << 10) + (g4c << 2);
            #pragma unroll
            for (int j = 0; j < 4; j++) {
                int gc = (g4c << 2) + j;
                if (is_border(grow, gc) && __ldg(&io[nb + j]) == -1)
                    vals[j] = RWG_ * __ldg(&bed[nb + j]);
            }
        }
        int sc = hc << 2;
        sS[hr][sc + 0] = vals[0];
        sS[hr][sc + 1] = vals[1];
        sS[hr][sc + 2] = vals[2];
        sS[hr][sc + 3] = vals[3];
    }
    __syncthreads();

    int r_i = threadIdx.x >> 5, c_i = threadIdx.x & 31;
    int g4c = col4 + c_i;
    int gc0 = g4c << 2;
    float ats = 0.f, att = 0.f, ar0s = 0.f, ar0t = 0.f;
    #pragma unroll
    for (int k = 0; k < 2; k++) {
        int grow = row0 + r_i + (k << 3);
        int i4 = (grow << 8) + g4c;
        float4 rv = ((const float4*)g_r)[i4];
        float4 vv = ((const float4*)v)[i4];
        float4 sc_raw;
        sc_raw.x = rv.x - al * vv.x;
        sc_raw.y = rv.y - al * vv.y;
        sc_raw.z = rv.z - al * vv.z;
        sc_raw.w = rv.w - al * vv.w;
        ((float4*)g_s)[i4] = sc_raw;

        int hr = r_i + 1 + (k << 3), sc = (c_i + 1) << 2;
        float4 t0;
        if (!edge) {
            #pragma unroll
            for (int j = 0; j < 4; j++) {
                float xc = sS[hr][sc + j];
                float a = (sS[hr][sc + j - 1] - xc);
                a += (sS[hr][sc + j + 1] - xc);
                a += (sS[hr - 1][sc + j] - xc);
                a += (sS[hr + 1][sc + j] - xc);
                ((float*)&t0)[j] = a * INV_DX2_;
            }
        } else {
            #pragma unroll
            for (int j = 0; j < 4; j++) {
                float xc = sS[hr][sc + j];
                float a = 0.f;
                int gc = gc0 + j;
                if (gc > 0)          a += sS[hr][sc + j - 1] - xc;
                if (gc < C_ - 1)     a += sS[hr][sc + j + 1] - xc;
                if (grow > 0)        a += sS[hr - 1][sc + j] - xc;
                if (grow < R_ - 1)   a += sS[hr + 1][sc + j] - xc;
                ((float*)&t0)[j] = a * INV_DX2_;
            }
        }
        ((float4*)g_t)[i4] = t0;
        float4 r0v = ((const float4*)g_r0)[i4];
        ats  += dot4f(t0, sc_raw);
        att  += dot4f(t0, t0);
        ar0s += dot4f(r0v, sc_raw);
        ar0t += dot4f(r0v, t0);
    }
    int slot = (it + 1) * NSLOT + (blockIdx.x & (NSLOT - 1));
    red4f(ats, att, ar0s, ar0t,
          &g_dts[slot], &g_dtt[slot], &g_dr0s[slot], &g_dr0t[slot]);
}

// ---------------- k_eff: eff per node (final x on the fly, float4) ---------
__global__ void __launch_bounds__(256) k_eff(const float* __restrict__ bed,
                                             const float* __restrict__ ob) {
    __shared__ float shs[2];
    if (threadIdx.x < 32) {
        int lane = threadIdx.x;
        // rho_of(15) from index 14; al14 = rho/dr0v[15]; om14 = dts[15]/dtt[15]
        double dts14  = wred(g_dts [(ITERS_ - 1) * NSLOT + lane]);
        double dtt14  = wred(g_dtt [(ITERS_ - 1) * NSLOT + lane]);
        double dr0s14 = wred(g_dr0s[(ITERS_ - 1) * NSLOT + lane]);
        double dr0t14 = wred(g_dr0t[(ITERS_ - 1) * NSLOT + lane]);
        double dr0v15 = wred(g_dr0v[ITERS_ * NSLOT + lane]);
        double dts15  = wred(g_dts [ITERS_ * NSLOT + lane]);
        double dtt15  = wred(g_dtt [ITERS_ * NSLOT + lane]);
        if (lane == 0) {
            double om_p = dts14 / (dtt14 + EPSD);
            double rho_n = dr0s14 - om_p * dr0t14;
            shs[0] = (float)(rho_n / (dr0v15 + EPSD));       // al14
            shs[1] = (float)(dts15 / (dtt15 + EPSD));        // om14
        }
    }
    __syncthreads();
    float al = shs[0], om = shs[1];

    int i4 = blockIdx.x * blockDim.x + threadIdx.x;   // over TOT4
    float4 xv = ((const float4*)g_x )[i4];
    float4 pv = ((const float4*)g_pB)[i4];   // final p buffer (pNew of it=14)
    float4 sv = ((const float4*)g_s )[i4];
    float4 bv = ((const float4*)bed)[i4];
    float4 ov = ((const float4*)ob )[i4];
    float4 e;
    #pragma unroll
    for (int j = 0; j < 4; j++) {
        float xf = (((const float*)&xv)[j] + al * ((const float*)&pv)[j])
                 + om * ((const float*)&sv)[j];
        float pd = xf - RWG_ * ((const float*)&bv)[j];
        float o  = ((const float*)&ov)[j];
        float wp = fminf(fmaxf(pd, 0.f), o);
        ((float*)&e)[j] = o - wp;
    }
    ((float4*)g_eff)[i4] = e;
}

// ---------------- epilogue: analytic topology, eff gathered -----------------
__global__ void __launch_bounds__(256) k_out(const float4* __restrict__ cs,
                                             const float4* __restrict__ q,
                                             const int4* __restrict__ fd,
                                             float4* __restrict__ out,
                                             const int* __restrict__ dtp) {
    int i = blockIdx.x * blockDim.x + threadIdx.x;   // over L_/4
    if (i >= L_ / 4) return;
    float dtf = (float)__ldg(dtp);
    float4 c4 = cs[i];
    float4 q4 = q[i];
    int4  f4 = fd[i];
    float4 g4 = ((const float4*)g_grad)[i];
    int l0 = i << 2;
    float4 o;
    #pragma unroll
    for (int j = 0; j < 4; j++) {
        int l = l0 + j;
        int tail, head;
        if (l < HL_) {
            int r = l / (C_ - 1);
            int c = l - r * (C_ - 1);
            tail = r * C_ + c;
            head = tail + 1;
        } else {
            tail = l - HL_;
            head = tail + C_;
        }
        float el = fmaxf(0.5f * (__ldg(&g_eff[head]) + __ldg(&g_eff[tail])), 1.0f);
        float csv = ((const float*)&c4)[j];
        float melt = A_OPEN_ * ((const float*)&q4)[j] * ((const float*)&g4)[j]
                   * (float)((const int*)&f4)[j];
        float closure = C_CLOSE_ * (el * el * el) * csv;
        ((float*)&o)[j] = fmaxf(csv + (melt - closure) * dtf, 0.001f);
    }
    out[i] = o;
}

// ---------------- launch ----------------
extern "C" void kernel_launch(void* const* d_in, const int* in_sizes, int n_in,
                              void* d_out, int out_size) {
    const float* cs   = (const float*)d_in[0];
    const float* q    = (const float*)d_in[1];
    const float* bed  = (const float*)d_in[2];
    const float* ob   = (const float*)d_in[3];
    const int*   fd   = (const int*)  d_in[4];
    const int*   io   = (const int*)  d_in[5];
    // d_in[6]=head, d_in[7]=tail unused (analytic raster topology)
    const int*   dtp  = (const int*)  d_in[8];
    float* out = (float*)d_out;

    const int TB = 256;
    const int GB_L4 = (L_ / 4 + TB - 1) / TB;  // 2046
    const int GB_4  = TOT4 / TB;               // 1024
    const int GB_T  = 512;                     // 64 x 8 tiles (single wave)

    k_grad<<<GB_L4, TB>>>((const float4*)cs, (const float4*)q, (const int4*)fd);
    k_init<<<GB_4, TB>>>(io, bed);

    for (int it = 0; it < ITERS_; ++it) {
        k_A<<<GB_T, TB>>>(io, bed, it);
        k_B<<<GB_T, TB>>>(io, bed, it);
    }

    k_eff<<<GB_4, TB>>>(bed, ob);
    k_out<<<GB_L4, TB>>>((const float4*)cs, (const float4*)q, (const int4*)fd,
                         (float4*)out, dtp);
}

// round 17
// speedup vs baseline: 1.2904x; 1.0307x over previous
#include <cuda_runtime.h>

// ---------------- problem constants (raster grid 1024x1024) ----------------
#define R_  1024
#define C_  1024
#define N_  (R_ * C_)
#define HL_ (R_ * (C_ - 1))          // horizontal links = 1,047,552
#define L_  (HL_ + (R_ - 1) * C_)    // total links = 2,095,104
#define ITERS_ 15
#define NSLOT 32
#define F4ROW (C_ / 4)               // 256 float4 per row
#define TOT4  (N_ / 4)               // 262144 float4 total

#define K_FLOW_  0.0405f
#define FLOW_EXP_ 1.25f
#define A_OPEN_  1.3455e-09f
#define C_CLOSE_ 7.11e-24f
#define RWG_     9810.0f             // rho_w * g
#define INV_DX_  (1.0f / 100.0f)
#define INV_DX2_ (1.0f / (100.0f * 100.0f))

// tile: 16 rows x 32 f4 (128 floats) per block; 512 blocks; halo 1 cell
#define SROWS 18
#define SCOLS 136
#define TSLOTS (18 * 34)             // 612 haloed f4 slots

// ---------------- device scratch (static; no allocations) ----------------
__device__ __align__(16) float g_x [N_];
__device__ __align__(16) float g_r [N_];
__device__ __align__(16) float g_pA[N_];
__device__ __align__(16) float g_pB[N_];
__device__ __align__(16) float g_vA[N_];
__device__ __align__(16) float g_vB[N_];
__device__ __align__(16) float g_s [N_];
__device__ __align__(16) float g_t [N_];
__device__ __align__(16) float g_r0[N_];
__device__ __align__(16) float g_eff[N_];
__device__ __align__(16) float g_grad[L_];

// scalar slots (32 contention-spread each)
__device__ double g_rho1[NSLOT];                    // rho[1] = dot(r0,r0)
__device__ double g_dr0v[(ITERS_ + 1) * NSLOT];     // [0]=1 ; [i+1]=dot(r0,v)
__device__ double g_dts [(ITERS_ + 1) * NSLOT];     // [0]=1 ; [i+1]=dot(t,s)
__device__ double g_dtt [(ITERS_ + 1) * NSLOT];     // [0]=1 ; [i+1]=dot(t,t)
__device__ double g_dr0s[(ITERS_ + 1) * NSLOT];     // [i+1]=dot(r0,s)
__device__ double g_dr0t[(ITERS_ + 1) * NSLOT];     // [i+1]=dot(r0,t)

#define EPSD 1e-30

// ---------------- warp-parallel f64 slot reduction (lane j owns slot j) ----
__device__ __forceinline__ double wred(double v) {
    #pragma unroll
    for (int o = 16; o > 0; o >>= 1) v += __shfl_down_sync(0xffffffffu, v, o);
    return v;   // valid in lane 0
}

// ---------------- block reductions: f32 to warp level, f64 above ----------
__device__ __forceinline__ void red1f(float v, double* dst) {
    #pragma unroll
    for (int o = 16; o > 0; o >>= 1) v += __shfl_down_sync(0xffffffffu, v, o);
    __shared__ double sm1[8];
    int lane = threadIdx.x & 31, w = threadIdx.x >> 5;
    if (lane == 0) sm1[w] = (double)v;
    __syncthreads();
    if (threadIdx.x < 8) {
        double d = sm1[threadIdx.x];
        #pragma unroll
        for (int o = 4; o > 0; o >>= 1) d += __shfl_down_sync(0xffu, d, o);
        if (threadIdx.x == 0) atomicAdd(dst, d);
    }
}

__device__ __forceinline__ void red4f(float a, float b, float c, float d,
                                      double* da, double* db, double* dc, double* dd) {
    #pragma unroll
    for (int o = 16; o > 0; o >>= 1) {
        a += __shfl_down_sync(0xffffffffu, a, o);
        b += __shfl_down_sync(0xffffffffu, b, o);
        c += __shfl_down_sync(0xffffffffu, c, o);
        d += __shfl_down_sync(0xffffffffu, d, o);
    }
    __shared__ double sma[8], smb[8], smc[8], smd[8];
    int lane = threadIdx.x & 31, w = threadIdx.x >> 5;
    if (lane == 0) { sma[w] = (double)a; smb[w] = (double)b;
                     smc[w] = (double)c; smd[w] = (double)d; }
    __syncthreads();
    if (threadIdx.x < 8) {
        double a_ = sma[threadIdx.x], b_ = smb[threadIdx.x];
        double c_ = smc[threadIdx.x], d_ = smd[threadIdx.x];
        #pragma unroll
        for (int o = 4; o > 0; o >>= 1) {
            a_ += __shfl_down_sync(0xffu, a_, o);
            b_ += __shfl_down_sync(0xffu, b_, o);
            c_ += __shfl_down_sync(0xffu, c_, o);
            d_ += __shfl_down_sync(0xffu, d_, o);
        }
        if (threadIdx.x == 0) {
            atomicAdd(da, a_); atomicAdd(db, b_);
            atomicAdd(dc, c_); atomicAdd(dd, d_);
        }
    }
}

__device__ __forceinline__ float dot4f(float4 a, float4 b) {
    return a.x * b.x + a.y * b.y + a.z * b.z + a.w * b.w;
}

__device__ __forceinline__ bool is_border(int r, int c) {
    return (r == 0 || r == R_ - 1 || c == 0 || c == C_ - 1);
}

// ---------------- prologue kernel: grad (float4) + scalar-slot init --------
__device__ __forceinline__ float pow125(float s) {
    return s * sqrtf(sqrtf(s));   // s^1.25
}

__global__ void __launch_bounds__(256) k_grad(const float4* __restrict__ cs,
                                              const float4* __restrict__ q,
                                              const int4* __restrict__ fd) {
    int i = blockIdx.x * blockDim.x + threadIdx.x;   // over L_/4
    if (blockIdx.x == 0) {
        for (int j = threadIdx.x; j < NSLOT; j += 256) g_rho1[j] = 0.0;
        for (int j = threadIdx.x; j < (ITERS_ + 1) * NSLOT; j += 256) {
            double v = (j == 0) ? 1.0 : 0.0;
            g_dr0v[j] = v; g_dts[j] = v; g_dtt[j] = v;
            g_dr0s[j] = 0.0; g_dr0t[j] = 0.0;
        }
    }
    if (i < L_ / 4) {
        float4 s = cs[i];
        float4 qq = q[i];
        int4  f = fd[i];
        float4 o;
        float gx = qq.x / (K_FLOW_ * pow125(s.x)); o.x = gx * gx * (float)f.x;
        float gy = qq.y / (K_FLOW_ * pow125(s.y)); o.y = gy * gy * (float)f.y;
        float gz = qq.z / (K_FLOW_ * pow125(s.z)); o.z = gz * gz * (float)f.z;
        float gw = qq.w / (K_FLOW_ * pow125(s.w)); o.w = gw * gw * (float)f.w;
        ((float4*)g_grad)[i] = o;
    }
}

// ---------------- init: r0 = b - A(0); zero x (pA/vA skipped: never read
//    before written — k_A0 does not touch them, k_A(it=1) writes pA/vA) -----
__device__ __forceinline__ float xb0v(const int* __restrict__ io,
                                      const float* __restrict__ bed, int r, int c) {
    if (is_border(r, c)) {
        int n = r * C_ + c;
        if (__ldg(&io[n]) == -1) return RWG_ * __ldg(&bed[n]);
    }
    return 0.f;
}

__global__ void __launch_bounds__(256) k_init(const int* __restrict__ io,
                                              const float* __restrict__ bed) {
    int i4 = blockIdx.x * blockDim.x + threadIdx.x;   // over TOT4
    int n = i4 << 2;
    int r = n >> 10, c0 = n & (C_ - 1);

    float4 gv  = make_float4(0.f, 0.f, 0.f, 0.f);
    float4 gvu = make_float4(0.f, 0.f, 0.f, 0.f);
    if (r < R_ - 1) gv  = ((const float4*)g_grad)[(HL_ + n) >> 2];
    if (r > 0)      gvu = ((const float4*)g_grad)[(HL_ + n - C_) >> 2];
    int hb = r * (C_ - 1);
    float ghm = (c0 > 0) ? __ldg(&g_grad[hb + c0 - 1]) : 0.f;
    float gh0 = __ldg(&g_grad[hb + c0 + 0]);
    float gh1 = __ldg(&g_grad[hb + c0 + 1]);
    float gh2 = __ldg(&g_grad[hb + c0 + 2]);
    float gh3 = (c0 + 3 < C_ - 1) ? __ldg(&g_grad[hb + c0 + 3]) : 0.f;

    float4 r0v;
    #pragma unroll
    for (int j = 0; j < 4; j++) {
        int c = c0 + j;
        float ghR = (j == 0) ? gh0 : (j == 1) ? gh1 : (j == 2) ? gh2 : gh3;
        float ghL = (j == 0) ? ghm : (j == 1) ? gh0 : (j == 2) ? gh1 : gh2;
        float gvD = ((const float*)&gv)[j];
        float gvU = ((const float*)&gvu)[j];
        float acc = 0.f;
        if (c < C_ - 1) acc += ghR;
        if (r < R_ - 1) acc += gvD;
        if (c > 0)      acc -= ghL;
        if (r > 0)      acc -= gvU;
        float b = acc * INV_DX_;
        float xc = xb0v(io, bed, r, c);
        float a = 0.f;
        if (c > 0)      a += xb0v(io, bed, r, c - 1) - xc;
        if (c < C_ - 1) a += xb0v(io, bed, r, c + 1) - xc;
        if (r > 0)      a += xb0v(io, bed, r - 1, c) - xc;
        if (r < R_ - 1) a += xb0v(io, bed, r + 1, c) - xc;
        ((float*)&r0v)[j] = b - a * INV_DX2_;
    }
    ((float4*)g_r0)[i4] = r0v;
    ((float4*)g_r )[i4] = r0v;
    ((float4*)g_x )[i4] = make_float4(0.f, 0.f, 0.f, 0.f);
    red1f(dot4f(r0v, r0v), &g_rho1[blockIdx.x & (NSLOT - 1)]);
}

// ---------------- K_A0 (it=0): p1 = r0 exactly (p=v=0 => r + beta*0 = r);
//    v1 = A(xb(r0)); dot(r0, v1). No scalars needed. -------------------------
__global__ void __launch_bounds__(256, 4) k_A0(const int* __restrict__ io,
                                               const float* __restrict__ bed) {
    float* __restrict__ pNew = g_pB;   // it=0, pp=0
    float* __restrict__ vNew = g_vB;

    __shared__ float sP[SROWS][SCOLS];
    int b = blockIdx.x;
    int tx = b & 7, ty = b >> 3;
    int row0 = ty << 4, col4 = tx << 5;
    bool edge = (ty == 0) || (ty == 63) || (tx == 0) || (tx == 7);

    for (int slot = threadIdx.x; slot < TSLOTS; slot += 256) {
        int hr = slot / 34, hc = slot - hr * 34;
        int grow = row0 - 1 + hr;
        int g4c  = col4 - 1 + hc;
        if ((unsigned)grow > (unsigned)(R_ - 1) ||
            (unsigned)g4c  > (unsigned)(F4ROW - 1)) continue;
        int i4 = (grow << 8) + g4c;
        float4 rn = ((const float4*)g_r)[i4];
        float vals[4] = {rn.x, rn.y, rn.z, rn.w};
        if (edge) {
            int nb = (grow << 10) + (g4c << 2);
            #pragma unroll
            for (int j = 0; j < 4; j++) {
                int gc = (g4c << 2) + j;
                if (is_border(grow, gc) && __ldg(&io[nb + j]) == -1)
                    vals[j] = RWG_ * __ldg(&bed[nb + j]);
            }
        }
        int sc = hc << 2;
        sP[hr][sc + 0] = vals[0];
        sP[hr][sc + 1] = vals[1];
        sP[hr][sc + 2] = vals[2];
        sP[hr][sc + 3] = vals[3];
    }
    __syncthreads();

    int r_i = threadIdx.x >> 5, c_i = threadIdx.x & 31;
    int g4c = col4 + c_i;
    int gc0 = g4c << 2;
    float acc = 0.f;
    #pragma unroll
    for (int k = 0; k < 2; k++) {
        int grow = row0 + r_i + (k << 3);
        int i4 = (grow << 8) + g4c;
        float4 rn = ((const float4*)g_r)[i4];
        ((float4*)pNew)[i4] = rn;

        int hr = r_i + 1 + (k << 3), sc = (c_i + 1) << 2;
        float4 vout;
        if (!edge) {
            #pragma unroll
            for (int j = 0; j < 4; j++) {
                float xc = sP[hr][sc + j];
                float a = (sP[hr][sc + j - 1] - xc);
                a += (sP[hr][sc + j + 1] - xc);
                a += (sP[hr - 1][sc + j] - xc);
                a += (sP[hr + 1][sc + j] - xc);
                ((float*)&vout)[j] = a * INV_DX2_;
            }
        } else {
            #pragma unroll
            for (int j = 0; j < 4; j++) {
                float xc = sP[hr][sc + j];
                float a = 0.f;
                int gc = gc0 + j;
                if (gc > 0)          a += sP[hr][sc + j - 1] - xc;
                if (gc < C_ - 1)     a += sP[hr][sc + j + 1] - xc;
                if (grow > 0)        a += sP[hr - 1][sc + j] - xc;
                if (grow < R_ - 1)   a += sP[hr + 1][sc + j] - xc;
                ((float*)&vout)[j] = a * INV_DX2_;
            }
        }
        ((float4*)vNew)[i4] = vout;
        acc += dot4f(((const float4*)g_r0)[i4], vout);
    }
    red1f(acc, &g_dr0v[1 * NSLOT + (blockIdx.x & (NSLOT - 1))]);
}

// ---------------- K_A (it>=1): r_cur = s - om_p*t ; x += al_p*p + om_p*s ;
//    p_new = r_cur + beta*(p_old - om_p*v_old) ; v_new = A(xb(p_new)) ;
//    dot(r0, v_new) --------------------------------------------------------
__global__ void __launch_bounds__(256, 4) k_A(const int* __restrict__ io,
                                              const float* __restrict__ bed,
                                              int it) {
    int pp = it & 1;
    const float* __restrict__ pOld = pp ? g_pB : g_pA;
    const float* __restrict__ vOld = pp ? g_vB : g_vA;
    float* __restrict__ pNew = pp ? g_pA : g_pB;
    float* __restrict__ vNew = pp ? g_vA : g_vB;

    __shared__ float sP[SROWS][SCOLS];
    __shared__ float shs[3];
    // warp-parallel scalar head: lane j owns slot j of each array (it >= 1)
    if (threadIdx.x < 32) {
        int lane = threadIdx.x;
        double dts_c  = wred(g_dts [it * NSLOT + lane]);
        double dtt_c  = wred(g_dtt [it * NSLOT + lane]);
        double dr0v_c = wred(g_dr0v[it * NSLOT + lane]);
        double dr0s_c = wred(g_dr0s[it * NSLOT + lane]);
        double dr0t_c = wred(g_dr0t[it * NSLOT + lane]);
        double rho_p;
        if (it == 1) {
            rho_p = wred(g_rho1[lane]);
        } else {
            double dts_p  = wred(g_dts [(it - 1) * NSLOT + lane]);
            double dtt_p  = wred(g_dtt [(it - 1) * NSLOT + lane]);
            double dr0s_p = wred(g_dr0s[(it - 1) * NSLOT + lane]);
            double dr0t_p = wred(g_dr0t[(it - 1) * NSLOT + lane]);
            double om_pp = dts_p / (dtt_p + EPSD);
            rho_p = dr0s_p - om_pp * dr0t_p;
        }
        if (lane == 0) {
            double om_p = dts_c / (dtt_c + EPSD);
            double al_p = rho_p / (dr0v_c + EPSD);
            double rho_n = dr0s_c - om_p * dr0t_c;
            shs[0] = (float)((rho_n / (rho_p + EPSD)) * (al_p / (om_p + EPSD)));
            shs[1] = (float)om_p;
            shs[2] = (float)al_p;
        }
    }
    __syncthreads();
    float beta = shs[0], om = shs[1], al = shs[2];

    int b = blockIdx.x;                  // 512 blocks: 64 tile-rows x 8 tile-cols
    int tx = b & 7, ty = b >> 3;
    int row0 = ty << 4, col4 = tx << 5;
    bool edge = (ty == 0) || (ty == 63) || (tx == 0) || (tx == 7);

    // fill smem with xb-substituted p_new over haloed region
    for (int slot = threadIdx.x; slot < TSLOTS; slot += 256) {
        int hr = slot / 34, hc = slot - hr * 34;
        int grow = row0 - 1 + hr;
        int g4c  = col4 - 1 + hc;
        if ((unsigned)grow > (unsigned)(R_ - 1) ||
            (unsigned)g4c  > (unsigned)(F4ROW - 1)) continue;
        int i4 = (grow << 8) + g4c;
        float4 pv = ((const float4*)pOld)[i4];
        float4 vv = ((const float4*)vOld)[i4];
        float4 sv = ((const float4*)g_s)[i4];
        float4 tv = ((const float4*)g_t)[i4];
        float4 rn;
        rn.x = sv.x - om * tv.x;  rn.y = sv.y - om * tv.y;
        rn.z = sv.z - om * tv.z;  rn.w = sv.w - om * tv.w;
        float vals[4];
        vals[0] = rn.x + beta * (pv.x - om * vv.x);
        vals[1] = rn.y + beta * (pv.y - om * vv.y);
        vals[2] = rn.z + beta * (pv.z - om * vv.z);
        vals[3] = rn.w + beta * (pv.w - om * vv.w);
        if (edge) {
            int nb = (grow << 10) + (g4c << 2);
            #pragma unroll
            for (int j = 0; j < 4; j++) {
                int gc = (g4c << 2) + j;
                if (is_border(grow, gc) && __ldg(&io[nb + j]) == -1)
                    vals[j] = RWG_ * __ldg(&bed[nb + j]);
            }
        }
        int sc = hc << 2;
        sP[hr][sc + 0] = vals[0];
        sP[hr][sc + 1] = vals[1];
        sP[hr][sc + 2] = vals[2];
        sP[hr][sc + 3] = vals[3];
    }
    __syncthreads();

    // two output rows per thread: r_i and r_i + 8
    int r_i = threadIdx.x >> 5, c_i = threadIdx.x & 31;
    int g4c = col4 + c_i;
    int gc0 = g4c << 2;
    float acc = 0.f;
    #pragma unroll
    for (int k = 0; k < 2; k++) {
        int grow = row0 + r_i + (k << 3);
        int i4 = (grow << 8) + g4c;
        float4 pv = ((const float4*)pOld)[i4];
        float4 vv = ((const float4*)vOld)[i4];
        float4 sv = ((const float4*)g_s)[i4];
        float4 tv = ((const float4*)g_t)[i4];
        float4 rn;
        rn.x = sv.x - om * tv.x;  rn.y = sv.y - om * tv.y;
        rn.z = sv.z - om * tv.z;  rn.w = sv.w - om * tv.w;
        ((float4*)g_r)[i4] = rn;
        // deferred x update of iteration it-1 (identical expression)
        float4 xv = ((const float4*)g_x)[i4];
        float4 xn;
        xn.x = (xv.x + al * pv.x) + om * sv.x;
        xn.y = (xv.y + al * pv.y) + om * sv.y;
        xn.z = (xv.z + al * pv.z) + om * sv.z;
        xn.w = (xv.w + al * pv.w) + om * sv.w;
        ((float4*)g_x)[i4] = xn;

        float4 pn;
        pn.x = rn.x + beta * (pv.x - om * vv.x);
        pn.y = rn.y + beta * (pv.y - om * vv.y);
        pn.z = rn.z + beta * (pv.z - om * vv.z);
        pn.w = rn.w + beta * (pv.w - om * vv.w);
        ((float4*)pNew)[i4] = pn;

        int hr = r_i + 1 + (k << 3), sc = (c_i + 1) << 2;
        float4 vout;
        if (!edge) {
            #pragma unroll
            for (int j = 0; j < 4; j++) {
                float xc = sP[hr][sc + j];
                float a = (sP[hr][sc + j - 1] - xc);
                a += (sP[hr][sc + j + 1] - xc);
                a += (sP[hr - 1][sc + j] - xc);
                a += (sP[hr + 1][sc + j] - xc);
                ((float*)&vout)[j] = a * INV_DX2_;
            }
        } else {
            #pragma unroll
            for (int j = 0; j < 4; j++) {
                float xc = sP[hr][sc + j];
                float a = 0.f;
                int gc = gc0 + j;
                if (gc > 0)          a += sP[hr][sc + j - 1] - xc;
                if (gc < C_ - 1)     a += sP[hr][sc + j + 1] - xc;
                if (grow > 0)        a += sP[hr - 1][sc + j] - xc;
                if (grow < R_ - 1)   a += sP[hr + 1][sc + j] - xc;
                ((float*)&vout)[j] = a * INV_DX2_;
            }
        }
        ((float4*)vNew)[i4] = vout;
        acc += dot4f(((const float4*)g_r0)[i4], vout);
    }
    red1f(acc, &g_dr0v[(it + 1) * NSLOT + (blockIdx.x & (NSLOT - 1))]);
}

// ---------------- K_B: s = r - al*v ; t = A(xb(s)) ;
//    dots (t,s),(t,t),(r0,s),(r0,t) -----------------------------------------
__global__ void __launch_bounds__(256, 4) k_B(const int* __restrict__ io,
                                              const float* __restrict__ bed,
                                              int it) {
    int pp = it & 1;
    const float* __restrict__ v = pp ? g_vA : g_vB;   // v_new of this iter

    __shared__ float sS[SROWS][SCOLS];
    __shared__ float shs[1];
    if (threadIdx.x < 32) {
        int lane = threadIdx.x;
        double dr0v_n = wred(g_dr0v[(it + 1) * NSLOT + lane]);
        double rho_n;
        if (it == 0) {
            rho_n = wred(g_rho1[lane]);
        } else {
            double dts_c  = wred(g_dts [it * NSLOT + lane]);
            double dtt_c  = wred(g_dtt [it * NSLOT + lane]);
            double dr0s_c = wred(g_dr0s[it * NSLOT + lane]);
            double dr0t_c = wred(g_dr0t[it * NSLOT + lane]);
            double om_p = dts_c / (dtt_c + EPSD);
            rho_n = dr0s_c - om_p * dr0t_c;
        }
        if (lane == 0)
            shs[0] = (float)(rho_n / (dr0v_n + EPSD));
    }
    __syncthreads();
    float al = shs[0];

    int b = blockIdx.x;
    int tx = b & 7, ty = b >> 3;
    int row0 = ty << 4, col4 = tx << 5;
    bool edge = (ty == 0) || (ty == 63) || (tx == 0) || (tx == 7);

    for (int slot = threadIdx.x; slot < TSLOTS; slot += 256) {
        int hr = slot / 34, hc = slot - hr * 34;
        int grow = row0 - 1 + hr;
        int g4c  = col4 - 1 + hc;
        if ((unsigned)grow > (unsigned)(R_ - 1) ||
            (unsigned)g4c  > (unsigned)(F4ROW - 1)) continue;
        int i4 = (grow << 8) + g4c;
        float4 rv = ((const float4*)g_r)[i4];
        float4 vv = ((const float4*)v)[i4];
        float vals[4];
        vals[0] = rv.x - al * vv.x;
        vals[1] = rv.y - al * vv.y;
        vals[2] = rv.z - al * vv.z;
        vals[3] = rv.w - al * vv.w;
        if (edge) {
            int nb = (grow << 10) + (g4c << 2);
            #pragma unroll
            for (int j = 0; j < 4; j++) {
                int gc = (g4c << 2) + j;
                if (is_border(grow, gc) && __ldg(&io[nb + j]) == -1)
                    vals[j] = RWG_ * __ldg(&bed[nb + j]);
            }
        }
        int sc = hc << 2;
        sS[hr][sc + 0] = vals[0];
        sS[hr][sc + 1] = vals[1];
        sS[hr][sc + 2] = vals[2];
        sS[hr][sc + 3] = vals[3];
    }
    __syncthreads();

    int r_i = threadIdx.x >> 5, c_i = threadIdx.x & 31;
    int g4c = col4 + c_i;
    int gc0 = g4c << 2;
    float ats = 0.f, att = 0.f, ar0s = 0.f, ar0t = 0.f;
    #pragma unroll
    for (int k = 0; k < 2; k++) {
        int grow = row0 + r_i + (k << 3);
        int i4 = (grow << 8) + g4c;
        float4 rv = ((const float4*)g_r)[i4];
        float4 vv = ((const float4*)v)[i4];
        float4 sc_raw;
        sc_raw.x = rv.x - al * vv.x;
        sc_raw.y = rv.y - al * vv.y;
        sc_raw.z = rv.z - al * vv.z;
        sc_raw.w = rv.w - al * vv.w;
        ((float4*)g_s)[i4] = sc_raw;

        int hr = r_i + 1 + (k << 3), sc = (c_i + 1) << 2;
        float4 t0;
        if (!edge) {
            #pragma unroll
            for (int j = 0; j < 4; j++) {
                float xc = sS[hr][sc + j];
                float a = (sS[hr][sc + j - 1] - xc);
                a += (sS[hr][sc + j + 1] - xc);
                a += (sS[hr - 1][sc + j] - xc);
                a += (sS[hr + 1][sc + j] - xc);
                ((float*)&t0)[j] = a * INV_DX2_;
            }
        } else {
            #pragma unroll
            for (int j = 0; j < 4; j++) {
                float xc = sS[hr][sc + j];
                float a = 0.f;
                int gc = gc0 + j;
                if (gc > 0)          a += sS[hr][sc + j - 1] - xc;
                if (gc < C_ - 1)     a += sS[hr][sc + j + 1] - xc;
                if (grow > 0)        a += sS[hr - 1][sc + j] - xc;
                if (grow < R_ - 1)   a += sS[hr + 1][sc + j] - xc;
                ((float*)&t0)[j] = a * INV_DX2_;
            }
        }
        ((float4*)g_t)[i4] = t0;
        float4 r0v = ((const float4*)g_r0)[i4];
        ats  += dot4f(t0, sc_raw);
        att  += dot4f(t0, t0);
        ar0s += dot4f(r0v, sc_raw);
        ar0t += dot4f(r0v, t0);
    }
    int slot = (it + 1) * NSLOT + (blockIdx.x & (NSLOT - 1));
    red4f(ats, att, ar0s, ar0t,
          &g_dts[slot], &g_dtt[slot], &g_dr0s[slot], &g_dr0t[slot]);
}

// ---------------- k_eff: eff per node (final x on the fly, float4) ---------
__global__ void __launch_bounds__(256) k_eff(const float* __restrict__ bed,
                                             const float* __restrict__ ob) {
    __shared__ float shs[2];
    if (threadIdx.x < 32) {
        int lane = threadIdx.x;
        double dts14  = wred(g_dts [(ITERS_ - 1) * NSLOT + lane]);
        double dtt14  = wred(g_dtt [(ITERS_ - 1) * NSLOT + lane]);
        double dr0s14 = wred(g_dr0s[(ITERS_ - 1) * NSLOT + lane]);
        double dr0t14 = wred(g_dr0t[(ITERS_ - 1) * NSLOT + lane]);
        double dr0v15 = wred(g_dr0v[ITERS_ * NSLOT + lane]);
        double dts15  = wred(g_dts [ITERS_ * NSLOT + lane]);
        double dtt15  = wred(g_dtt [ITERS_ * NSLOT + lane]);
        if (lane == 0) {
            double om_p = dts14 / (dtt14 + EPSD);
            double rho_n = dr0s14 - om_p * dr0t14;
            shs[0] = (float)(rho_n / (dr0v15 + EPSD));       // al14
            shs[1] = (float)(dts15 / (dtt15 + EPSD));        // om14
        }
    }
    __syncthreads();
    float al = shs[0], om = shs[1];

    int i4 = blockIdx.x * blockDim.x + threadIdx.x;   // over TOT4
    float4 xv = ((const float4*)g_x )[i4];
    float4 pv = ((const float4*)g_pB)[i4];   // final p buffer (pNew of it=14)
    float4 sv = ((const float4*)g_s )[i4];
    float4 bv = ((const float4*)bed)[i4];
    float4 ov = ((const float4*)ob )[i4];
    float4 e;
    #pragma unroll
    for (int j = 0; j < 4; j++) {
        float xf = (((const float*)&xv)[j] + al * ((const float*)&pv)[j])
                 + om * ((const float*)&sv)[j];
        float pd = xf - RWG_ * ((const float*)&bv)[j];
        float o  = ((const float*)&ov)[j];
        float wp = fminf(fmaxf(pd, 0.f), o);
        ((float*)&e)[j] = o - wp;
    }
    ((float4*)g_eff)[i4] = e;
}

// ---------------- epilogue: analytic topology, eff gathered.
//    melt = A*q*grad*fd = A*q*|grad| bitwise (fd in {-1,+1}, grad = g^2*fd) --
__global__ void __launch_bounds__(256) k_out(const float4* __restrict__ cs,
                                             const float4* __restrict__ q,
                                             float4* __restrict__ out,
                                             const int* __restrict__ dtp) {
    int i = blockIdx.x * blockDim.x + threadIdx.x;   // over L_/4
    if (i >= L_ / 4) return;
    float dtf = (float)__ldg(dtp);
    float4 c4 = cs[i];
    float4 q4 = q[i];
    float4 g4 = ((const float4*)g_grad)[i];
    int l0 = i << 2;
    float4 o;
    #pragma unroll
    for (int j = 0; j < 4; j++) {
        int l = l0 + j;
        int tail, head;
        if (l < HL_) {
            int r = l / (C_ - 1);
            int c = l - r * (C_ - 1);
            tail = r * C_ + c;
            head = tail + 1;
        } else {
            tail = l - HL_;
            head = tail + C_;
        }
        float el = fmaxf(0.5f * (__ldg(&g_eff[head]) + __ldg(&g_eff[tail])), 1.0f);
        float csv = ((const float*)&c4)[j];
        float melt = A_OPEN_ * ((const float*)&q4)[j] * fabsf(((const float*)&g4)[j]);
        float closure = C_CLOSE_ * (el * el * el) * csv;
        ((float*)&o)[j] = fmaxf(csv + (melt - closure) * dtf, 0.001f);
    }
    out[i] = o;
}

// ---------------- launch ----------------
extern "C" void kernel_launch(void* const* d_in, const int* in_sizes, int n_in,
                              void* d_out, int out_size) {
    const float* cs   = (const float*)d_in[0];
    const float* q    = (const float*)d_in[1];
    const float* bed  = (const float*)d_in[2];
    const float* ob   = (const float*)d_in[3];
    const int*   fd   = (const int*)  d_in[4];
    const int*   io   = (const int*)  d_in[5];
    // d_in[6]=head, d_in[7]=tail unused (analytic raster topology)
    const int*   dtp  = (const int*)  d_in[8];
    float* out = (float*)d_out;

    const int TB = 256;
    const int GB_L4 = (L_ / 4 + TB - 1) / TB;  // 2046
    const int GB_4  = TOT4 / TB;               // 1024
    const int GB_T  = 512;                     // 64 x 8 tiles (single wave)

    k_grad<<<GB_L4, TB>>>((const float4*)cs, (const float4*)q, (const int4*)fd);
    k_init<<<GB_4, TB>>>(io, bed);

    k_A0<<<GB_T, TB>>>(io, bed);
    k_B <<<GB_T, TB>>>(io, bed, 0);
    for (int it = 1; it < ITERS_; ++it) {
        k_A<<<GB_T, TB>>>(io, bed, it);
        k_B<<<GB_T, TB>>>(io, bed, it);
    }

    k_eff<<<GB_4, TB>>>(bed, ob);
    k_out<<<GB_L4, TB>>>((const float4*)cs, (const float4*)q,
                         (float4*)out, dtp);
}